// round 13
// baseline (speedup 1.0000x reference)
#include <cuda_runtime.h>
#include <cuda_fp16.h>
#include <cstdint>

#define T_  3
#define H_  96
#define W_  96
#define C_  128
#define CK  128
#define NHEAD 8
#define DH  16
#define HW_ (H_*W_)
#define NT  (T_*HW_)        // 27648
#define QX  4
#define YSEG 16
#define XS (W_/QX)
#define YB (H_/YSEG)
#define NSLOT 6

// fp16 K/V smem layout: row = 128 halves = 256B data + 16B pad
#define HROW 272
#define SLICEB (24*HROW)
#define ATTN_SMEM (12*SLICEB + 25*HROW)   // 85136

typedef unsigned long long u64;

extern __shared__ char smraw[];

// fp16 packed pairs (half2 per uint32): 64 per row of 128
__device__ uint32_t g_Qh[NT*64], g_Kh[NT*64], g_Vh[NT*64], g_Oh[NT*64];
__device__ uint32_t g_sph[25*64];
__device__ uint32_t g_xh[NT*64];
__device__ uint32_t g_Whh[4][128*64], g_Whl[4][128*64];   // [k][n-pairs], fp16 hi/lo

// ---------------- helpers ----------------
__device__ __forceinline__ u64 ffma2(u64 a, u64 b, u64 c) {
    u64 d; asm("fma.rn.f32x2 %0,%1,%2,%3;" : "=l"(d) : "l"(a), "l"(b), "l"(c)); return d;
}
__device__ __forceinline__ u64 fadd2(u64 a, u64 b) {
    u64 d; asm("add.rn.f32x2 %0,%1,%2;" : "=l"(d) : "l"(a), "l"(b)); return d;
}
__device__ __forceinline__ u64 pack2(float lo, float hi) {
    u64 d; asm("mov.b64 %0,{%1,%2};" : "=l"(d) : "f"(lo), "f"(hi)); return d;
}
__device__ __forceinline__ float2 unpack2(u64 v) {
    float2 r; asm("mov.b64 {%0,%1},%2;" : "=f"(r.x), "=f"(r.y) : "l"(v)); return r;
}
__device__ __forceinline__ void cp16(uint32_t dst, const void* src) {
    asm volatile("cp.async.cg.shared.global [%0], [%1], 16;" :: "r"(dst), "l"(src));
}
__device__ __forceinline__ float ex2(float t) {
    float e; asm("ex2.approx.f32 %0, %1;" : "=f"(e) : "f"(t)); return e;
}
__device__ __forceinline__ uint32_t h2pack(float x0, float x1) {
    __half2 h = __float22half2_rn(make_float2(x0, x1));
    return *reinterpret_cast<uint32_t*>(&h);
}
#define H2(u) (*reinterpret_cast<const __half2*>(&(u)))

// ---------------- mma helpers ----------------
__device__ __forceinline__ void ldsm_x4(uint32_t* a, uint32_t addr) {
    asm volatile("ldmatrix.sync.aligned.m8n8.x4.shared.b16 {%0,%1,%2,%3}, [%4];"
                 : "=r"(a[0]), "=r"(a[1]), "=r"(a[2]), "=r"(a[3]) : "r"(addr));
}
__device__ __forceinline__ void ldsm_x2t(uint32_t* b, uint32_t addr) {
    asm volatile("ldmatrix.sync.aligned.m8n8.x2.trans.shared.b16 {%0,%1}, [%2];"
                 : "=r"(b[0]), "=r"(b[1]) : "r"(addr));
}
__device__ __forceinline__ void mma16816(float* c, const uint32_t* a, const uint32_t* b) {
    asm volatile(
        "mma.sync.aligned.m16n8k16.row.col.f32.f16.f16.f32 "
        "{%0,%1,%2,%3}, {%4,%5,%6,%7}, {%8,%9}, {%0,%1,%2,%3};"
        : "+f"(c[0]), "+f"(c[1]), "+f"(c[2]), "+f"(c[3])
        : "r"(a[0]), "r"(a[1]), "r"(a[2]), "r"(a[3]), "r"(b[0]), "r"(b[1]));
}

// smem: Bh | Bl | A0 | A1, each 128 rows x 272 bytes
#define BROW 272
#define TILE_B (128*BROW)
#define BH_OFF 0
#define BL_OFF TILE_B
#define A0_OFF (2*TILE_B)
#define GEMM_SMEM (4*TILE_B)    // 139264

// ---------------------------------------------------------------------------
// prep kernels
// ---------------------------------------------------------------------------
__global__ __launch_bounds__(256) void xprep_kernel(const float* __restrict__ x) {
    int i = blockIdx.x * 256 + threadIdx.x;
    float4 v = *(const float4*)&x[(size_t)i * 4];
    *(uint2*)&g_xh[i * 2] = make_uint2(h2pack(v.x, v.y), h2pack(v.z, v.w));
}

__global__ __launch_bounds__(256) void wprep_kernel(
    const float* __restrict__ Wq, const float* __restrict__ Wk,
    const float* __restrict__ Wv, const float* __restrict__ Wo,
    const float* __restrict__ sp_emb)
{
    const int mat = blockIdx.x;
    if (mat == 4) {
        for (int i = threadIdx.x; i < 25 * 64; i += 256) {
            float2 v = *(const float2*)&sp_emb[(size_t)i * 2];
            g_sph[i] = h2pack(v.x, v.y);
        }
        return;
    }
    const float* Wsrc = (mat == 0) ? Wq : (mat == 1) ? Wk : (mat == 2) ? Wv : Wo;
    for (int p = threadIdx.x; p < 128 * 64; p += 256) {
        float2 v = *(const float2*)&Wsrc[(size_t)p * 2];
        __half h0 = __float2half_rn(v.x);
        __half h1 = __float2half_rn(v.y);
        __half l0 = __float2half_rn(v.x - __half2float(h0));
        __half l1 = __float2half_rn(v.y - __half2float(h1));
        g_Whh[mat][p] = ((uint32_t)__half_as_ushort(h1) << 16) | __half_as_ushort(h0);
        g_Whl[mat][p] = ((uint32_t)__half_as_ushort(l1) << 16) | __half_as_ushort(l0);
    }
}

// ---------------------------------------------------------------------------
// Persistent GEMM helpers
// ---------------------------------------------------------------------------
__device__ __forceinline__ void fill_B(uint32_t sb, int mat, int tid) {
#pragma unroll
    for (int it = 0; it < 8; it++) {
        int i = tid + it * 256;
        int r = i >> 4, ch = i & 15;
        uint32_t d = (uint32_t)(r * BROW + ch * 16);
        cp16(sb + BH_OFF + d, (const char*)&g_Whh[mat][r * 64 + ch * 4]);
        cp16(sb + BL_OFF + d, (const char*)&g_Whl[mat][r * 64 + ch * 4]);
    }
}
__device__ __forceinline__ void fill_A(uint32_t sb, uint32_t aoff,
                                       const uint32_t* __restrict__ A, int m0, int tid) {
#pragma unroll
    for (int it = 0; it < 8; it++) {
        int i = tid + it * 256;
        int r = i >> 4, ch = i & 15;
        uint32_t d = (uint32_t)(r * BROW + ch * 16);
        cp16(sb + aoff + d, (const char*)A + ((size_t)(m0 + r) * 64 + ch * 4) * 4);
    }
}

// compute c = A(buf) @ [Bh; Bl] (2 passes), B resident. warp tile 32m x 64n.
__device__ __forceinline__ void gemm_compute(uint32_t sb, int cur, int w, int lane,
                                             float c[2][8][4]) {
#pragma unroll
    for (int mt = 0; mt < 2; mt++)
#pragma unroll
        for (int nt = 0; nt < 8; nt++)
#pragma unroll
            for (int j = 0; j < 4; j++) c[mt][nt][j] = 0.f;

    const int wm = w & 3, wn = w >> 2;
    const uint32_t aBase = sb + (uint32_t)(A0_OFF + cur * TILE_B)
                         + (uint32_t)((wm * 32 + (lane & 15)) * BROW + (lane >> 4) * 16);
    const uint32_t bBase = sb + (uint32_t)((lane & 15) * BROW + wn * 128);

#pragma unroll
    for (int pass = 0; pass < 2; pass++) {
        const uint32_t bT = bBase + (pass ? BL_OFF : BH_OFF);
#pragma unroll
        for (int k8 = 0; k8 < 8; k8++) {
            uint32_t a[2][4], b[8][2];
#pragma unroll
            for (int mt = 0; mt < 2; mt++)
                ldsm_x4(a[mt], aBase + (uint32_t)(mt * 16 * BROW + k8 * 32));
#pragma unroll
            for (int nt = 0; nt < 8; nt++)
                ldsm_x2t(b[nt], bT + (uint32_t)(k8 * 16 * BROW + nt * 16));
#pragma unroll
            for (int mt = 0; mt < 2; mt++)
#pragma unroll
                for (int nt = 0; nt < 8; nt++)
                    mma16816(c[mt][nt], a[mt], b[nt]);
        }
    }
}

// ---------------------------------------------------------------------------
// Kernel: QKV persistent GEMM. grid (48, 3). Tiles bx + 48*i.
// ---------------------------------------------------------------------------
__global__ __launch_bounds__(256, 1) void qkv_mma_kernel(
    const float* __restrict__ temp_emb, const float* __restrict__ sp_emb)
{
    const int mat = blockIdx.y;
    const int bx  = blockIdx.x;
    const int ntiles = 4 + (bx < 24 ? 1 : 0);
    const int tid = threadIdx.x;
    const int w = tid >> 5, lane = tid & 31;
    const int wm = w & 3, wn = w >> 2;
    const uint32_t sb = (uint32_t)__cvta_generic_to_shared(smraw);
    uint32_t* dsth = (mat == 0) ? g_Qh : (mat == 1) ? g_Kh : g_Vh;

    fill_B(sb, mat, tid);
    fill_A(sb, A0_OFF, g_xh, bx * 128, tid);
    asm volatile("cp.async.commit_group;");
    asm volatile("cp.async.wait_group 0;");
    __syncthreads();

    int cur = 0;
    for (int ti = 0; ti < ntiles; ti++) {
        const int m0 = (bx + ti * 48) * 128;
        const bool hasnext = (ti + 1 < ntiles);
        if (hasnext) {
            fill_A(sb, A0_OFF + (1 - cur) * TILE_B, g_xh, (bx + (ti + 1) * 48) * 128, tid);
            asm volatile("cp.async.commit_group;");
        }

        float c[2][8][4];
        gemm_compute(sb, cur, w, lane, c);

        // epilogue
#pragma unroll
        for (int mt = 0; mt < 2; mt++) {
#pragma unroll
            for (int rh = 0; rh < 2; rh++) {
                const int n   = m0 + wm * 32 + mt * 16 + (lane >> 2) + rh * 8;
                const int t   = n / HW_;
                const int rem = n % HW_;
                int qidx = 0;
                if (mat == 0) {
                    const int yq = rem / W_, xq = rem % W_;
                    const int yc = min(max(yq, 2), H_ - 3);
                    const int xc = min(max(xq, 2), W_ - 3);
                    qidx = (yq - yc + 2) * 5 + (xq - xc + 2);
                }
#pragma unroll
                for (int nt = 0; nt < 8; nt++) {
                    const int col = wn * 64 + nt * 8 + 2 * (lane & 3);
                    float v0 = c[mt][nt][rh * 2 + 0];
                    float v1 = c[mt][nt][rh * 2 + 1];
                    if (mat <= 1) {
                        v0 += temp_emb[t * CK + col];
                        v1 += temp_emb[t * CK + col + 1];
                    }
                    if (mat == 0) {
                        v0 += sp_emb[qidx * CK + col];
                        v1 += sp_emb[qidx * CK + col + 1];
                    }
                    dsth[(size_t)n * 64 + (col >> 1)] = h2pack(v0, v1);
                }
            }
        }

        if (hasnext) asm volatile("cp.async.wait_group 0;");
        __syncthreads();
        cur ^= 1;
    }
}

// ---------------------------------------------------------------------------
// Kernel: output projection persistent GEMM. grid 108, 2 tiles each.
// ---------------------------------------------------------------------------
__global__ __launch_bounds__(256, 1) void outproj_mma_kernel(float* __restrict__ out)
{
    const int bx  = blockIdx.x;
    const int tid = threadIdx.x;
    const int w = tid >> 5, lane = tid & 31;
    const int wm = w & 3, wn = w >> 2;
    const uint32_t sb = (uint32_t)__cvta_generic_to_shared(smraw);

    fill_B(sb, 3, tid);
    fill_A(sb, A0_OFF, g_Oh, bx * 128, tid);
    asm volatile("cp.async.commit_group;");
    asm volatile("cp.async.wait_group 0;");
    __syncthreads();

    int cur = 0;
#pragma unroll
    for (int ti = 0; ti < 2; ti++) {
        const int m0 = (bx + ti * 108) * 128;
        const bool hasnext = (ti == 0);
        if (hasnext) {
            fill_A(sb, A0_OFF + (1 - cur) * TILE_B, g_Oh, (bx + 108) * 128, tid);
            asm volatile("cp.async.commit_group;");
        }

        float c[2][8][4];
        gemm_compute(sb, cur, w, lane, c);

#pragma unroll
        for (int mt = 0; mt < 2; mt++) {
#pragma unroll
            for (int rh = 0; rh < 2; rh++) {
                const int n   = m0 + wm * 32 + mt * 16 + (lane >> 2) + rh * 8;
                const int t   = n / HW_;
                const int rem = n % HW_;
                const size_t ob = (size_t)rem * (T_ * C_) + t * C_;
#pragma unroll
                for (int nt = 0; nt < 8; nt++) {
                    const int col = wn * 64 + nt * 8 + 2 * (lane & 3);
                    *(float2*)&out[ob + col] =
                        make_float2(c[mt][nt][rh * 2 + 0], c[mt][nt][rh * 2 + 1]);
                }
            }
        }

        if (hasnext) asm volatile("cp.async.wait_group 0;");
        __syncthreads();
        cur ^= 1;
    }
}

// ---------------------------------------------------------------------------
// Kernel: attention, rolling-window persistent blocks, fp16 everywhere (R12).
// ---------------------------------------------------------------------------
__global__ __launch_bounds__(768) void attn_kernel()
{
    char* Krh = smraw;                       // 6 x SLICEB
    char* Vrh = smraw + 6 * SLICEB;          // 6 x SLICEB
    char* SPh = smraw + 12 * SLICEB;         // 25 x HROW

    const uint32_t sbase = (uint32_t)__cvta_generic_to_shared(smraw);
    const uint32_t Kb0 = sbase;
    const uint32_t Vb0 = sbase + 6 * SLICEB;
    const uint32_t SPb = sbase + 12 * SLICEB;

    const int x0  = blockIdx.x * QX;
    const int y0  = blockIdx.y * YSEG;
    const int tid = threadIdx.x;
    const int xbase = min(max(x0, 2), W_ - 3) - 2;

    const bool isV = tid >= 384;
    const int j    = isV ? tid - 384 : tid;
    const int grow = j >> 4;
    const int gch  = j & 15;
    const int gt   = grow >> 3;
    const int gcol = min(xbase + (grow & 7), W_ - 1);
    const size_t sgbase = (size_t)(gt * HW_ + gcol) * 64 + gch * 4;
    const uint32_t ssoff = (uint32_t)(grow * HROW + gch * 16);
    const uint32_t* gsrc = isV ? g_Vh : g_Kh;
    const uint32_t sdstb = isV ? Vb0 : Kb0;

    if (tid < 400) {
        int r = tid >> 4, ch = tid & 15;
        cp16(SPb + (uint32_t)(r * HROW + ch * 16), &g_sph[r * 64 + ch * 4]);
    }
    const int yc0 = min(max(y0, 2), H_ - 3);
#pragma unroll
    for (int r = 0; r < 5; r++) {
        const int yr = yc0 - 2 + r;
        cp16(sdstb + (uint32_t)((yr % NSLOT) * SLICEB) + ssoff,
             &gsrc[sgbase + (size_t)yr * W_ * 64]);
    }
    asm volatile("cp.async.commit_group;");
    asm volatile("cp.async.wait_group 0;");
    __syncthreads();
    int loaded_max = yc0 + 2;

    const int lane = tid & 31;
    const int w    = tid >> 5;
    const int tq   = w / NHEAD;
    const int h    = w % NHEAD;
    const int hb   = h << 5;

    const int qx  = lane >> 3;
    const int rl  = lane & 7;
    const int xoffq = min(max(x0 + qx, 2), W_ - 3) - 2 - xbase;
    const int kxr   = rl - xoffq;
    const bool valid = (kxr >= 0) && (kxr <= 4);
    const int kxrc  = min(max(kxr, 0), 4);
    const int d4 = lane >> 3;

    const float L2S = 0.36067376022224085f;   // 0.25 * log2(e)

    for (int yq = y0; yq < y0 + YSEG; yq++) {
        const int yc = min(max(yq, 2), H_ - 3);

        const int need_next = min(max(yq + 1, 2), H_ - 3) + 2;
        const bool pf = (yq + 1 < y0 + YSEG) && (need_next > loaded_max);
        if (pf) {
            cp16(sdstb + (uint32_t)((need_next % NSLOT) * SLICEB) + ssoff,
                 &gsrc[sgbase + (size_t)need_next * W_ * 64]);
            asm volatile("cp.async.commit_group;");
            loaded_max = need_next;
        }

        int slot[5];
        {
            int s0 = (yc - 2) % NSLOT;
#pragma unroll
            for (int i5 = 0; i5 < 5; i5++) {
                slot[i5] = s0;
                s0 = (s0 + 1 == NSLOT) ? 0 : s0 + 1;
            }
        }

        const uint4* qp = (const uint4*)&g_Qh[(size_t)(tq * HW_ + yq * W_ + x0 + qx) * 64 + (h << 3)];
        uint4 qa = qp[0], qb = qp[1];
        __half2 q2[8] = {H2(qa.x), H2(qa.y), H2(qa.z), H2(qa.w),
                         H2(qb.x), H2(qb.y), H2(qb.z), H2(qb.w)};

        float a[15];
#pragma unroll
        for (int tk = 0; tk < 3; tk++) {
#pragma unroll
            for (int i5 = 0; i5 < 5; i5++) {
                const char* kr = Krh + slot[i5] * SLICEB + (tk * 8 + rl) * HROW + hb;
                uint4 ka = *(const uint4*)kr;
                uint4 kb = *(const uint4*)(kr + 16);
                __half2 s2 = __hmul2(q2[0], H2(ka.x));
                s2 = __hfma2(q2[1], H2(ka.y), s2);
                s2 = __hfma2(q2[2], H2(ka.z), s2);
                s2 = __hfma2(q2[3], H2(ka.w), s2);
                s2 = __hfma2(q2[4], H2(kb.x), s2);
                s2 = __hfma2(q2[5], H2(kb.y), s2);
                s2 = __hfma2(q2[6], H2(kb.z), s2);
                s2 = __hfma2(q2[7], H2(kb.w), s2);
                float2 f = __half22float2(s2);
                a[tk * 5 + i5] = f.x + f.y;
            }
        }

        float qsp[5];
#pragma unroll
        for (int i5 = 0; i5 < 5; i5++) {
            const char* sp = SPh + (i5 * 5 + kxrc) * HROW + hb;
            uint4 sa = *(const uint4*)sp;
            uint4 sb2 = *(const uint4*)(sp + 16);
            __half2 s2 = __hmul2(q2[0], H2(sa.x));
            s2 = __hfma2(q2[1], H2(sa.y), s2);
            s2 = __hfma2(q2[2], H2(sa.z), s2);
            s2 = __hfma2(q2[3], H2(sa.w), s2);
            s2 = __hfma2(q2[4], H2(sb2.x), s2);
            s2 = __hfma2(q2[5], H2(sb2.y), s2);
            s2 = __hfma2(q2[6], H2(sb2.z), s2);
            s2 = __hfma2(q2[7], H2(sb2.w), s2);
            float2 f = __half22float2(s2);
            qsp[i5] = f.x + f.y;
        }

        float ssum = 0.f;
#pragma unroll
        for (int tk = 0; tk < 3; tk++)
#pragma unroll
            for (int i5 = 0; i5 < 5; i5++) {
                int idx = tk * 5 + i5;
                float e = ex2((a[idx] + qsp[i5]) * L2S);
                e = valid ? e : 0.f;
                a[idx] = e;
                ssum += e;
            }
        ssum += __shfl_xor_sync(0xffffffffu, ssum, 1);
        ssum += __shfl_xor_sync(0xffffffffu, ssum, 2);
        ssum += __shfl_xor_sync(0xffffffffu, ssum, 4);
        float rs = __fdividef(1.f, ssum);

        u64 acc[4][2];
#pragma unroll
        for (int q = 0; q < 4; q++) { acc[q][0] = 0ull; acc[q][1] = 0ull; }

#pragma unroll
        for (int tk = 0; tk < 3; tk++) {
#pragma unroll
            for (int i5 = 0; i5 < 5; i5++) {
                const int idx = tk * 5 + i5;
                const char* vr = Vrh + slot[i5] * SLICEB + (tk * 8 + rl) * HROW + hb + (d4 << 3);
                uint2 vv = *(const uint2*)vr;
                float2 va = __half22float2(H2(vv.x));
                float2 vb = __half22float2(H2(vv.y));
                u64 vx = pack2(va.x, va.y);
                u64 vy = pack2(vb.x, vb.y);
#pragma unroll
                for (int q = 0; q < 4; q++) {
                    float av = __shfl_sync(0xffffffffu, a[idx], (q << 3) | rl);
                    u64 aa = pack2(av, av);
                    acc[q][0] = ffma2(aa, vx, acc[q][0]);
                    acc[q][1] = ffma2(aa, vy, acc[q][1]);
                }
            }
        }
#pragma unroll
        for (int off = 1; off <= 4; off <<= 1) {
#pragma unroll
            for (int q = 0; q < 4; q++) {
                acc[q][0] = fadd2(acc[q][0], __shfl_xor_sync(0xffffffffu, acc[q][0], off));
                acc[q][1] = fadd2(acc[q][1], __shfl_xor_sync(0xffffffffu, acc[q][1], off));
            }
        }
        float rsw = __shfl_sync(0xffffffffu, rs, (lane & 7) * 8);
        if (rl < 4) {
            float2 lo = unpack2(acc[rl][0]);
            float2 hi = unpack2(acc[rl][1]);
            const int n = tq * HW_ + yq * W_ + x0 + rl;
            *(uint2*)&g_Oh[(size_t)n * 64 + (h << 3) + d4 * 2] =
                make_uint2(h2pack(lo.x * rsw, lo.y * rsw),
                           h2pack(hi.x * rsw, hi.y * rsw));
        }

        if (pf) asm volatile("cp.async.wait_group 0;");
        __syncthreads();
    }
}

// ---------------------------------------------------------------------------
extern "C" void kernel_launch(void* const* d_in, const int* in_sizes, int n_in,
                              void* d_out, int out_size)
{
    const float* x    = (const float*)d_in[0];
    const float* Wq   = (const float*)d_in[1];
    const float* Wk   = (const float*)d_in[2];
    const float* Wv   = (const float*)d_in[3];
    const float* Wo   = (const float*)d_in[4];
    const float* temp = (const float*)d_in[5];
    const float* sp   = (const float*)d_in[6];
    float* out = (float*)d_out;

    cudaFuncSetAttribute(qkv_mma_kernel, cudaFuncAttributeMaxDynamicSharedMemorySize, GEMM_SMEM);
    cudaFuncSetAttribute(outproj_mma_kernel, cudaFuncAttributeMaxDynamicSharedMemorySize, GEMM_SMEM);
    cudaFuncSetAttribute(attn_kernel, cudaFuncAttributeMaxDynamicSharedMemorySize, ATTN_SMEM);

    xprep_kernel<<<NT * 32 / 256, 256>>>(x);
    wprep_kernel<<<5, 256>>>(Wq, Wk, Wv, Wo, sp);
    qkv_mma_kernel<<<dim3(48, 3), 256, GEMM_SMEM>>>(temp, sp);

    attn_kernel<<<dim3(XS, YB), 768, ATTN_SMEM>>>();

    outproj_mma_kernel<<<108, 256, GEMM_SMEM>>>(out);
}

// round 14
// speedup vs baseline: 1.0915x; 1.0915x over previous
#include <cuda_runtime.h>
#include <cuda_fp16.h>
#include <cstdint>

#define T_  3
#define H_  96
#define W_  96
#define C_  128
#define CK  128
#define NHEAD 8
#define DH  16
#define HW_ (H_*W_)
#define NT  (T_*HW_)        // 27648
#define QX  4
#define YSEG 16
#define XS (W_/QX)
#define YB (H_/YSEG)
#define NSLOT 6

// fp16 K/V smem layout: row = 128 halves = 256B data + 16B pad
#define HROW 272
#define SLICEB (24*HROW)
#define ATTN_SMEM (12*SLICEB + 25*HROW)   // 85136

typedef unsigned long long u64;

extern __shared__ char smraw[];

// fp16 packed pairs (half2 per uint32): 64 per row of 128
__device__ uint32_t g_Qh[NT*64], g_Kh[NT*64], g_Vh[NT*64], g_Oh[NT*64];
__device__ uint32_t g_sph[25*64];
__device__ uint32_t g_xh[NT*64];
__device__ uint32_t g_Whh[4][128*64], g_Whl[4][128*64];   // [k][n-pairs], fp16 hi/lo

// ---------------- helpers ----------------
__device__ __forceinline__ u64 fadd2(u64 a, u64 b) {
    u64 d; asm("add.rn.f32x2 %0,%1,%2;" : "=l"(d) : "l"(a), "l"(b)); return d;
}
__device__ __forceinline__ u64 fmul2(u64 a, u64 b) {
    u64 d; asm("mul.rn.f32x2 %0,%1,%2;" : "=l"(d) : "l"(a), "l"(b)); return d;
}
__device__ __forceinline__ u64 pack2(float lo, float hi) {
    u64 d; asm("mov.b64 %0,{%1,%2};" : "=l"(d) : "f"(lo), "f"(hi)); return d;
}
__device__ __forceinline__ float2 unpack2(u64 v) {
    float2 r; asm("mov.b64 {%0,%1},%2;" : "=f"(r.x), "=f"(r.y) : "l"(v)); return r;
}
__device__ __forceinline__ void cp16(uint32_t dst, const void* src) {
    asm volatile("cp.async.cg.shared.global [%0], [%1], 16;" :: "r"(dst), "l"(src));
}
__device__ __forceinline__ float ex2(float t) {
    float e; asm("ex2.approx.f32 %0, %1;" : "=f"(e) : "f"(t)); return e;
}
__device__ __forceinline__ uint32_t h2pack(float x0, float x1) {
    __half2 h = __float22half2_rn(make_float2(x0, x1));
    return *reinterpret_cast<uint32_t*>(&h);
}
#define H2(u) (*reinterpret_cast<const __half2*>(&(u)))

// ---------------- mma helpers ----------------
__device__ __forceinline__ void ldsm_x4(uint32_t* a, uint32_t addr) {
    asm volatile("ldmatrix.sync.aligned.m8n8.x4.shared.b16 {%0,%1,%2,%3}, [%4];"
                 : "=r"(a[0]), "=r"(a[1]), "=r"(a[2]), "=r"(a[3]) : "r"(addr));
}
__device__ __forceinline__ void ldsm_x2t(uint32_t* b, uint32_t addr) {
    asm volatile("ldmatrix.sync.aligned.m8n8.x2.trans.shared.b16 {%0,%1}, [%2];"
                 : "=r"(b[0]), "=r"(b[1]) : "r"(addr));
}
__device__ __forceinline__ void mma16816(float* c, const uint32_t* a, const uint32_t* b) {
    asm volatile(
        "mma.sync.aligned.m16n8k16.row.col.f32.f16.f16.f32 "
        "{%0,%1,%2,%3}, {%4,%5,%6,%7}, {%8,%9}, {%0,%1,%2,%3};"
        : "+f"(c[0]), "+f"(c[1]), "+f"(c[2]), "+f"(c[3])
        : "r"(a[0]), "r"(a[1]), "r"(a[2]), "r"(a[3]), "r"(b[0]), "r"(b[1]));
}

#define BROW 272
#define TILE_B (128*BROW)
#define A_OFF  0
#define BH_OFF TILE_B
#define BL_OFF (2*TILE_B)
#define GEMM_SMEM (3*TILE_B)    // 104448

// ---------------------------------------------------------------------------
// prep kernels
// ---------------------------------------------------------------------------
__global__ __launch_bounds__(256) void xprep_kernel(const float* __restrict__ x) {
    int i = blockIdx.x * 256 + threadIdx.x;
    float4 v = *(const float4*)&x[(size_t)i * 4];
    *(uint2*)&g_xh[i * 2] = make_uint2(h2pack(v.x, v.y), h2pack(v.z, v.w));
}

__global__ __launch_bounds__(256) void wprep_kernel(
    const float* __restrict__ Wq, const float* __restrict__ Wk,
    const float* __restrict__ Wv, const float* __restrict__ Wo,
    const float* __restrict__ sp_emb)
{
    const int mat = blockIdx.x;
    if (mat == 4) {
        for (int i = threadIdx.x; i < 25 * 64; i += 256) {
            float2 v = *(const float2*)&sp_emb[(size_t)i * 2];
            g_sph[i] = h2pack(v.x, v.y);
        }
        return;
    }
    const float* Wsrc = (mat == 0) ? Wq : (mat == 1) ? Wk : (mat == 2) ? Wv : Wo;
    for (int p = threadIdx.x; p < 128 * 64; p += 256) {
        float2 v = *(const float2*)&Wsrc[(size_t)p * 2];
        __half h0 = __float2half_rn(v.x);
        __half h1 = __float2half_rn(v.y);
        __half l0 = __float2half_rn(v.x - __half2float(h0));
        __half l1 = __float2half_rn(v.y - __half2float(h1));
        g_Whh[mat][p] = ((uint32_t)__half_as_ushort(h1) << 16) | __half_as_ushort(h0);
        g_Whl[mat][p] = ((uint32_t)__half_as_ushort(l1) << 16) | __half_as_ushort(l0);
    }
}

// ---------------------------------------------------------------------------
// Shared MMA body (R12): fp16 2-pass (A*Bh + A*Bl). c[2][8][4] per warp.
// ---------------------------------------------------------------------------
__device__ __forceinline__ void mma_body(
    const uint32_t* __restrict__ A, int mat, int m0, float c[2][8][4])
{
    const int tid  = threadIdx.x;
    const int w    = tid >> 5;
    const int lane = tid & 31;
    const uint32_t sb = (uint32_t)__cvta_generic_to_shared(smraw);

#pragma unroll
    for (int it = 0; it < 8; it++) {
        int i = tid + it * 256;
        int r = i >> 4, ch = i & 15;
        uint32_t d = (uint32_t)(r * BROW + ch * 16);
        cp16(sb + A_OFF + d, (const char*)A + ((size_t)(m0 + r) * 64 + ch * 4) * 4);
        cp16(sb + BH_OFF + d, (const char*)&g_Whh[mat][r * 64 + ch * 4]);
    }
    asm volatile("cp.async.commit_group;");
#pragma unroll
    for (int it = 0; it < 8; it++) {
        int i = tid + it * 256;
        int r = i >> 4, ch = i & 15;
        uint32_t d = (uint32_t)(r * BROW + ch * 16);
        cp16(sb + BL_OFF + d, (const char*)&g_Whl[mat][r * 64 + ch * 4]);
    }
    asm volatile("cp.async.commit_group;");

#pragma unroll
    for (int mt = 0; mt < 2; mt++)
#pragma unroll
        for (int nt = 0; nt < 8; nt++)
#pragma unroll
            for (int j = 0; j < 4; j++) c[mt][nt][j] = 0.f;

    const int wm = w & 3, wn = w >> 2;
    const uint32_t aBase = sb + A_OFF + (uint32_t)((wm * 32 + (lane & 15)) * BROW + (lane >> 4) * 16);
    const uint32_t bBase = sb + (uint32_t)((lane & 15) * BROW + wn * 128);
    const uint32_t bOffP[2] = {BH_OFF, BL_OFF};

    asm volatile("cp.async.wait_group 1;");
    __syncthreads();

#pragma unroll
    for (int pass = 0; pass < 2; pass++) {
        if (pass == 1) {
            asm volatile("cp.async.wait_group 0;");
            __syncthreads();
        }
        const uint32_t bT = bBase + bOffP[pass];
#pragma unroll
        for (int k8 = 0; k8 < 8; k8++) {
            uint32_t a[2][4], b[8][2];
#pragma unroll
            for (int mt = 0; mt < 2; mt++)
                ldsm_x4(a[mt], aBase + (uint32_t)(mt * 16 * BROW + k8 * 32));
#pragma unroll
            for (int nt = 0; nt < 8; nt++)
                ldsm_x2t(b[nt], bT + (uint32_t)(k8 * 16 * BROW + nt * 16));
#pragma unroll
            for (int mt = 0; mt < 2; mt++)
#pragma unroll
                for (int nt = 0; nt < 8; nt++)
                    mma16816(c[mt][nt], a[mt], b[nt]);
        }
    }
}

// ---------------------------------------------------------------------------
// Kernel: QKV via mma.sync. Q/K/V -> fp16 half2 pairs. grid (216, 3)
// ---------------------------------------------------------------------------
__global__ __launch_bounds__(256, 1) void qkv_mma_kernel(
    const float* __restrict__ temp_emb, const float* __restrict__ sp_emb)
{
    const int mat = blockIdx.y;
    const int m0 = blockIdx.x * 128;

    float c[2][8][4];
    mma_body(g_xh, mat, m0, c);

    const int w = threadIdx.x >> 5, lane = threadIdx.x & 31;
    const int wm = w & 3, wn = w >> 2;
    uint32_t* dsth = (mat == 0) ? g_Qh : (mat == 1) ? g_Kh : g_Vh;
#pragma unroll
    for (int mt = 0; mt < 2; mt++) {
#pragma unroll
        for (int rh = 0; rh < 2; rh++) {
            const int n   = m0 + wm * 32 + mt * 16 + (lane >> 2) + rh * 8;
            const int t   = n / HW_;
            const int rem = n % HW_;
            int qidx = 0;
            if (mat == 0) {
                const int yq = rem / W_, xq = rem % W_;
                const int yc = min(max(yq, 2), H_ - 3);
                const int xc = min(max(xq, 2), W_ - 3);
                qidx = (yq - yc + 2) * 5 + (xq - xc + 2);
            }
#pragma unroll
            for (int nt = 0; nt < 8; nt++) {
                const int col = wn * 64 + nt * 8 + 2 * (lane & 3);
                float v0 = c[mt][nt][rh * 2 + 0];
                float v1 = c[mt][nt][rh * 2 + 1];
                if (mat <= 1) {
                    v0 += temp_emb[t * CK + col];
                    v1 += temp_emb[t * CK + col + 1];
                }
                if (mat == 0) {
                    v0 += sp_emb[qidx * CK + col];
                    v1 += sp_emb[qidx * CK + col + 1];
                }
                dsth[(size_t)n * 64 + (col >> 1)] = h2pack(v0, v1);
            }
        }
    }
}

// ---------------------------------------------------------------------------
// Kernel: output projection via mma.sync + transposed writeout. grid 216
// ---------------------------------------------------------------------------
__global__ __launch_bounds__(256, 1) void outproj_mma_kernel(float* __restrict__ out)
{
    const int m0 = blockIdx.x * 128;

    float c[2][8][4];
    mma_body(g_Oh, 3, m0, c);

    const int w = threadIdx.x >> 5, lane = threadIdx.x & 31;
    const int wm = w & 3, wn = w >> 2;
#pragma unroll
    for (int mt = 0; mt < 2; mt++) {
#pragma unroll
        for (int rh = 0; rh < 2; rh++) {
            const int n   = m0 + wm * 32 + mt * 16 + (lane >> 2) + rh * 8;
            const int t   = n / HW_;
            const int rem = n % HW_;
            const size_t ob = (size_t)rem * (T_ * C_) + t * C_;
#pragma unroll
            for (int nt = 0; nt < 8; nt++) {
                const int col = wn * 64 + nt * 8 + 2 * (lane & 3);
                *(float2*)&out[ob + col] =
                    make_float2(c[mt][nt][rh * 2 + 0], c[mt][nt][rh * 2 + 1]);
            }
        }
    }
}

// ---------------------------------------------------------------------------
// Kernel: attention. Phase 2 rewritten: lane owns its query (same layout as
// phase 1) -> no weight shuffles; HFMA2 accumulation per tk-group.
// ---------------------------------------------------------------------------
__global__ __launch_bounds__(768) void attn_kernel()
{
    char* Krh = smraw;                       // 6 x SLICEB
    char* Vrh = smraw + 6 * SLICEB;          // 6 x SLICEB
    char* SPh = smraw + 12 * SLICEB;         // 25 x HROW

    const uint32_t sbase = (uint32_t)__cvta_generic_to_shared(smraw);
    const uint32_t Kb0 = sbase;
    const uint32_t Vb0 = sbase + 6 * SLICEB;
    const uint32_t SPb = sbase + 12 * SLICEB;

    const int x0  = blockIdx.x * QX;
    const int y0  = blockIdx.y * YSEG;
    const int tid = threadIdx.x;
    const int xbase = min(max(x0, 2), W_ - 3) - 2;

    const bool isV = tid >= 384;
    const int j    = isV ? tid - 384 : tid;
    const int grow = j >> 4;
    const int gch  = j & 15;
    const int gt   = grow >> 3;
    const int gcol = min(xbase + (grow & 7), W_ - 1);
    const size_t sgbase = (size_t)(gt * HW_ + gcol) * 64 + gch * 4;
    const uint32_t ssoff = (uint32_t)(grow * HROW + gch * 16);
    const uint32_t* gsrc = isV ? g_Vh : g_Kh;
    const uint32_t sdstb = isV ? Vb0 : Kb0;

    if (tid < 400) {
        int r = tid >> 4, ch = tid & 15;
        cp16(SPb + (uint32_t)(r * HROW + ch * 16), &g_sph[r * 64 + ch * 4]);
    }
    const int yc0 = min(max(y0, 2), H_ - 3);
#pragma unroll
    for (int r = 0; r < 5; r++) {
        const int yr = yc0 - 2 + r;
        cp16(sdstb + (uint32_t)((yr % NSLOT) * SLICEB) + ssoff,
             &gsrc[sgbase + (size_t)yr * W_ * 64]);
    }
    asm volatile("cp.async.commit_group;");
    asm volatile("cp.async.wait_group 0;");
    __syncthreads();
    int loaded_max = yc0 + 2;

    const int lane = tid & 31;
    const int w    = tid >> 5;
    const int tq   = w / NHEAD;
    const int h    = w % NHEAD;
    const int hb   = h << 5;        // byte offset within fp16 row

    const int qx  = lane >> 3;
    const int rl  = lane & 7;
    const int xoffq = min(max(x0 + qx, 2), W_ - 3) - 2 - xbase;
    const int kxr   = rl - xoffq;
    const bool valid = (kxr >= 0) && (kxr <= 4);
    const int kxrc  = min(max(kxr, 0), 4);

    const float L2S = 0.36067376022224085f;   // 0.25 * log2(e)

    for (int yq = y0; yq < y0 + YSEG; yq++) {
        const int yc = min(max(yq, 2), H_ - 3);

        const int need_next = min(max(yq + 1, 2), H_ - 3) + 2;
        const bool pf = (yq + 1 < y0 + YSEG) && (need_next > loaded_max);
        if (pf) {
            cp16(sdstb + (uint32_t)((need_next % NSLOT) * SLICEB) + ssoff,
                 &gsrc[sgbase + (size_t)need_next * W_ * 64]);
            asm volatile("cp.async.commit_group;");
            loaded_max = need_next;
        }

        int slot[5];
        {
            int s0 = (yc - 2) % NSLOT;
#pragma unroll
            for (int i5 = 0; i5 < 5; i5++) {
                slot[i5] = s0;
                s0 = (s0 + 1 == NSLOT) ? 0 : s0 + 1;
            }
        }

        // Q: fp16 direct from gmem (2 x LDG.128)
        const uint4* qp = (const uint4*)&g_Qh[(size_t)(tq * HW_ + yq * W_ + x0 + qx) * 64 + (h << 3)];
        uint4 qa = qp[0], qb = qp[1];
        __half2 q2[8] = {H2(qa.x), H2(qa.y), H2(qa.z), H2(qa.w),
                         H2(qb.x), H2(qb.y), H2(qb.z), H2(qb.w)};

        // phase 1: Q.K (fp16 dot, fp32 combine)
        float a[15];
#pragma unroll
        for (int tk = 0; tk < 3; tk++) {
#pragma unroll
            for (int i5 = 0; i5 < 5; i5++) {
                const char* kr = Krh + slot[i5] * SLICEB + (tk * 8 + rl) * HROW + hb;
                uint4 ka = *(const uint4*)kr;
                uint4 kb = *(const uint4*)(kr + 16);
                __half2 s2 = __hmul2(q2[0], H2(ka.x));
                s2 = __hfma2(q2[1], H2(ka.y), s2);
                s2 = __hfma2(q2[2], H2(ka.z), s2);
                s2 = __hfma2(q2[3], H2(ka.w), s2);
                s2 = __hfma2(q2[4], H2(kb.x), s2);
                s2 = __hfma2(q2[5], H2(kb.y), s2);
                s2 = __hfma2(q2[6], H2(kb.z), s2);
                s2 = __hfma2(q2[7], H2(kb.w), s2);
                float2 f = __half22float2(s2);
                a[tk * 5 + i5] = f.x + f.y;
            }
        }

        float qsp[5];
#pragma unroll
        for (int i5 = 0; i5 < 5; i5++) {
            const char* sp = SPh + (i5 * 5 + kxrc) * HROW + hb;
            uint4 sa = *(const uint4*)sp;
            uint4 sb2 = *(const uint4*)(sp + 16);
            __half2 s2 = __hmul2(q2[0], H2(sa.x));
            s2 = __hfma2(q2[1], H2(sa.y), s2);
            s2 = __hfma2(q2[2], H2(sa.z), s2);
            s2 = __hfma2(q2[3], H2(sa.w), s2);
            s2 = __hfma2(q2[4], H2(sb2.x), s2);
            s2 = __hfma2(q2[5], H2(sb2.y), s2);
            s2 = __hfma2(q2[6], H2(sb2.z), s2);
            s2 = __hfma2(q2[7], H2(sb2.w), s2);
            float2 f = __half22float2(s2);
            qsp[i5] = f.x + f.y;
        }

        // exp + sum; weights kept as broadcast half2 for phase 2
        __half2 a2[15];
        float ssum = 0.f;
#pragma unroll
        for (int tk = 0; tk < 3; tk++)
#pragma unroll
            for (int i5 = 0; i5 < 5; i5++) {
                int idx = tk * 5 + i5;
                float e = ex2((a[idx] + qsp[i5]) * L2S);
                e = valid ? e : 0.f;
                ssum += e;
                a2[idx] = __floats2half2_rn(e, e);
            }
        ssum += __shfl_xor_sync(0xffffffffu, ssum, 1);
        ssum += __shfl_xor_sync(0xffffffffu, ssum, 2);
        ssum += __shfl_xor_sync(0xffffffffu, ssum, 4);
        float rs = __fdividef(1.f, ssum);

        // phase 2: AV — lane owns query qx, rows rl+8i, all 16 d.
        // HFMA2 accumulate per tk group (5 terms), then f32x2 combine.
        u64 facc[8];
#pragma unroll
        for (int i = 0; i < 8; i++) facc[i] = 0ull;

#pragma unroll
        for (int tk = 0; tk < 3; tk++) {
            __half2 hc[8];
#pragma unroll
            for (int i = 0; i < 8; i++) hc[i] = __floats2half2_rn(0.f, 0.f);
#pragma unroll
            for (int i5 = 0; i5 < 5; i5++) {
                const char* vr = Vrh + slot[i5] * SLICEB + (tk * 8 + rl) * HROW + hb;
                uint4 va = *(const uint4*)vr;
                uint4 vb = *(const uint4*)(vr + 16);
                __half2 aa = a2[tk * 5 + i5];
                hc[0] = __hfma2(aa, H2(va.x), hc[0]);
                hc[1] = __hfma2(aa, H2(va.y), hc[1]);
                hc[2] = __hfma2(aa, H2(va.z), hc[2]);
                hc[3] = __hfma2(aa, H2(va.w), hc[3]);
                hc[4] = __hfma2(aa, H2(vb.x), hc[4]);
                hc[5] = __hfma2(aa, H2(vb.y), hc[5]);
                hc[6] = __hfma2(aa, H2(vb.z), hc[6]);
                hc[7] = __hfma2(aa, H2(vb.w), hc[7]);
            }
#pragma unroll
            for (int i = 0; i < 8; i++) {
                float2 f = __half22float2(hc[i]);
                facc[i] = fadd2(facc[i], pack2(f.x, f.y));
            }
        }
        // reduce over the 8 rl lanes (same query)
#pragma unroll
        for (int off = 1; off <= 4; off <<= 1)
#pragma unroll
            for (int i = 0; i < 8; i++)
                facc[i] = fadd2(facc[i], __shfl_xor_sync(0xffffffffu, facc[i], off));

        // lane rl writes d-pair rl (7-SEL mux); rs is lane-resident
        u64 m0v = (rl & 1) ? facc[1] : facc[0];
        u64 m1v = (rl & 1) ? facc[3] : facc[2];
        u64 m2v = (rl & 1) ? facc[5] : facc[4];
        u64 m3v = (rl & 1) ? facc[7] : facc[6];
        u64 n0v = (rl & 2) ? m1v : m0v;
        u64 n1v = (rl & 2) ? m3v : m2v;
        u64 sv  = (rl & 4) ? n1v : n0v;
        sv = fmul2(sv, pack2(rs, rs));
        float2 pv = unpack2(sv);
        const int n = tq * HW_ + yq * W_ + x0 + qx;
        g_Oh[(size_t)n * 64 + (h << 3) + rl] = h2pack(pv.x, pv.y);

        if (pf) asm volatile("cp.async.wait_group 0;");
        __syncthreads();
    }
}

// ---------------------------------------------------------------------------
extern "C" void kernel_launch(void* const* d_in, const int* in_sizes, int n_in,
                              void* d_out, int out_size)
{
    const float* x    = (const float*)d_in[0];
    const float* Wq   = (const float*)d_in[1];
    const float* Wk   = (const float*)d_in[2];
    const float* Wv   = (const float*)d_in[3];
    const float* Wo   = (const float*)d_in[4];
    const float* temp = (const float*)d_in[5];
    const float* sp   = (const float*)d_in[6];
    float* out = (float*)d_out;

    cudaFuncSetAttribute(qkv_mma_kernel, cudaFuncAttributeMaxDynamicSharedMemorySize, GEMM_SMEM);
    cudaFuncSetAttribute(outproj_mma_kernel, cudaFuncAttributeMaxDynamicSharedMemorySize, GEMM_SMEM);
    cudaFuncSetAttribute(attn_kernel, cudaFuncAttributeMaxDynamicSharedMemorySize, ATTN_SMEM);

    xprep_kernel<<<NT * 32 / 256, 256>>>(x);
    wprep_kernel<<<5, 256>>>(Wq, Wk, Wv, Wo, sp);
    qkv_mma_kernel<<<dim3(NT / 128, 3), 256, GEMM_SMEM>>>(temp, sp);

    attn_kernel<<<dim3(XS, YB), 768, ATTN_SMEM>>>();

    outproj_mma_kernel<<<NT / 128, 256, GEMM_SMEM>>>(out);
}

// round 15
// speedup vs baseline: 1.1137x; 1.0203x over previous
#include <cuda_runtime.h>
#include <cuda_fp16.h>
#include <cstdint>

#define T_  3
#define H_  96
#define W_  96
#define C_  128
#define CK  128
#define NHEAD 8
#define DH  16
#define HW_ (H_*W_)
#define NT  (T_*HW_)        // 27648
#define QX  4
#define YSEG 8              // y rows per block (2 CTAs/SM variant)
#define XS (W_/QX)          // 24
#define YB (H_/YSEG)        // 12
#define NSLOT 6

// fp16 K/V smem layout: row = 128 halves = 256B data + 16B pad
#define HROW 272
#define SLICEB (24*HROW)
#define ATTN_SMEM (12*SLICEB + 25*HROW)   // 85136

typedef unsigned long long u64;

extern __shared__ char smraw[];

// fp16 packed pairs (half2 per uint32): 64 per row of 128
__device__ uint32_t g_Qh[NT*64], g_Kh[NT*64], g_Vh[NT*64], g_Oh[NT*64];
__device__ uint32_t g_sph[25*64];
__device__ uint32_t g_xh[NT*64];
__device__ uint32_t g_Whh[4][128*64], g_Whl[4][128*64];   // [k][n-pairs], fp16 hi/lo

// ---------------- helpers ----------------
__device__ __forceinline__ u64 fadd2(u64 a, u64 b) {
    u64 d; asm("add.rn.f32x2 %0,%1,%2;" : "=l"(d) : "l"(a), "l"(b)); return d;
}
__device__ __forceinline__ u64 fmul2(u64 a, u64 b) {
    u64 d; asm("mul.rn.f32x2 %0,%1,%2;" : "=l"(d) : "l"(a), "l"(b)); return d;
}
__device__ __forceinline__ u64 pack2(float lo, float hi) {
    u64 d; asm("mov.b64 %0,{%1,%2};" : "=l"(d) : "f"(lo), "f"(hi)); return d;
}
__device__ __forceinline__ float2 unpack2(u64 v) {
    float2 r; asm("mov.b64 {%0,%1},%2;" : "=f"(r.x), "=f"(r.y) : "l"(v)); return r;
}
__device__ __forceinline__ void cp16(uint32_t dst, const void* src) {
    asm volatile("cp.async.cg.shared.global [%0], [%1], 16;" :: "r"(dst), "l"(src));
}
__device__ __forceinline__ float ex2(float t) {
    float e; asm("ex2.approx.f32 %0, %1;" : "=f"(e) : "f"(t)); return e;
}
__device__ __forceinline__ uint32_t h2pack(float x0, float x1) {
    __half2 h = __float22half2_rn(make_float2(x0, x1));
    return *reinterpret_cast<uint32_t*>(&h);
}
#define H2(u) (*reinterpret_cast<const __half2*>(&(u)))

// ---------------- mma helpers ----------------
__device__ __forceinline__ void ldsm_x4(uint32_t* a, uint32_t addr) {
    asm volatile("ldmatrix.sync.aligned.m8n8.x4.shared.b16 {%0,%1,%2,%3}, [%4];"
                 : "=r"(a[0]), "=r"(a[1]), "=r"(a[2]), "=r"(a[3]) : "r"(addr));
}
__device__ __forceinline__ void ldsm_x2t(uint32_t* b, uint32_t addr) {
    asm volatile("ldmatrix.sync.aligned.m8n8.x2.trans.shared.b16 {%0,%1}, [%2];"
                 : "=r"(b[0]), "=r"(b[1]) : "r"(addr));
}
__device__ __forceinline__ void mma16816(float* c, const uint32_t* a, const uint32_t* b) {
    asm volatile(
        "mma.sync.aligned.m16n8k16.row.col.f32.f16.f16.f32 "
        "{%0,%1,%2,%3}, {%4,%5,%6,%7}, {%8,%9}, {%0,%1,%2,%3};"
        : "+f"(c[0]), "+f"(c[1]), "+f"(c[2]), "+f"(c[3])
        : "r"(a[0]), "r"(a[1]), "r"(a[2]), "r"(a[3]), "r"(b[0]), "r"(b[1]));
}

#define BROW 272
#define TILE_B (128*BROW)
#define A_OFF  0
#define BH_OFF TILE_B
#define BL_OFF (2*TILE_B)
#define GEMM_SMEM (3*TILE_B)    // 104448

#define L2S 0.36067376022224085f   // 0.25 * log2(e)

// ---------------------------------------------------------------------------
// prep kernel: blocks [0, NX) do x conversion; blocks [NX, NX+5) do W/sp.
// ---------------------------------------------------------------------------
#define NXB (NT*32/256)
__global__ __launch_bounds__(256) void prep_kernel(
    const float* __restrict__ x,
    const float* __restrict__ Wq, const float* __restrict__ Wk,
    const float* __restrict__ Wv, const float* __restrict__ Wo,
    const float* __restrict__ sp_emb)
{
    const int b = blockIdx.x;
    if (b < NXB) {
        int i = b * 256 + threadIdx.x;
        float4 v = *(const float4*)&x[(size_t)i * 4];
        *(uint2*)&g_xh[i * 2] = make_uint2(h2pack(v.x, v.y), h2pack(v.z, v.w));
        return;
    }
    const int mat = b - NXB;
    if (mat == 4) {
        for (int i = threadIdx.x; i < 25 * 64; i += 256) {
            float2 v = *(const float2*)&sp_emb[(size_t)i * 2];
            g_sph[i] = h2pack(v.x, v.y);
        }
        return;
    }
    const float* Wsrc = (mat == 0) ? Wq : (mat == 1) ? Wk : (mat == 2) ? Wv : Wo;
    for (int p = threadIdx.x; p < 128 * 64; p += 256) {
        float2 v = *(const float2*)&Wsrc[(size_t)p * 2];
        __half h0 = __float2half_rn(v.x);
        __half h1 = __float2half_rn(v.y);
        __half l0 = __float2half_rn(v.x - __half2float(h0));
        __half l1 = __float2half_rn(v.y - __half2float(h1));
        g_Whh[mat][p] = ((uint32_t)__half_as_ushort(h1) << 16) | __half_as_ushort(h0);
        g_Whl[mat][p] = ((uint32_t)__half_as_ushort(l1) << 16) | __half_as_ushort(l0);
    }
}

// ---------------------------------------------------------------------------
// Shared MMA body (R12): fp16 2-pass (A*Bh + A*Bl). c[2][8][4] per warp.
// ---------------------------------------------------------------------------
__device__ __forceinline__ void mma_body(
    const uint32_t* __restrict__ A, int mat, int m0, float c[2][8][4])
{
    const int tid  = threadIdx.x;
    const int w    = tid >> 5;
    const int lane = tid & 31;
    const uint32_t sb = (uint32_t)__cvta_generic_to_shared(smraw);

#pragma unroll
    for (int it = 0; it < 8; it++) {
        int i = tid + it * 256;
        int r = i >> 4, ch = i & 15;
        uint32_t d = (uint32_t)(r * BROW + ch * 16);
        cp16(sb + A_OFF + d, (const char*)A + ((size_t)(m0 + r) * 64 + ch * 4) * 4);
        cp16(sb + BH_OFF + d, (const char*)&g_Whh[mat][r * 64 + ch * 4]);
    }
    asm volatile("cp.async.commit_group;");
#pragma unroll
    for (int it = 0; it < 8; it++) {
        int i = tid + it * 256;
        int r = i >> 4, ch = i & 15;
        uint32_t d = (uint32_t)(r * BROW + ch * 16);
        cp16(sb + BL_OFF + d, (const char*)&g_Whl[mat][r * 64 + ch * 4]);
    }
    asm volatile("cp.async.commit_group;");

#pragma unroll
    for (int mt = 0; mt < 2; mt++)
#pragma unroll
        for (int nt = 0; nt < 8; nt++)
#pragma unroll
            for (int j = 0; j < 4; j++) c[mt][nt][j] = 0.f;

    const int wm = w & 3, wn = w >> 2;
    const uint32_t aBase = sb + A_OFF + (uint32_t)((wm * 32 + (lane & 15)) * BROW + (lane >> 4) * 16);
    const uint32_t bBase = sb + (uint32_t)((lane & 15) * BROW + wn * 128);
    const uint32_t bOffP[2] = {BH_OFF, BL_OFF};

    asm volatile("cp.async.wait_group 1;");
    __syncthreads();

#pragma unroll
    for (int pass = 0; pass < 2; pass++) {
        if (pass == 1) {
            asm volatile("cp.async.wait_group 0;");
            __syncthreads();
        }
        const uint32_t bT = bBase + bOffP[pass];
#pragma unroll
        for (int k8 = 0; k8 < 8; k8++) {
            uint32_t a[2][4], b[8][2];
#pragma unroll
            for (int mt = 0; mt < 2; mt++)
                ldsm_x4(a[mt], aBase + (uint32_t)(mt * 16 * BROW + k8 * 32));
#pragma unroll
            for (int nt = 0; nt < 8; nt++)
                ldsm_x2t(b[nt], bT + (uint32_t)(k8 * 16 * BROW + nt * 16));
#pragma unroll
            for (int mt = 0; mt < 2; mt++)
#pragma unroll
                for (int nt = 0; nt < 8; nt++)
                    mma16816(c[mt][nt], a[mt], b[nt]);
        }
    }
}

// ---------------------------------------------------------------------------
// Kernel: QKV via mma.sync. Q pre-scaled by L2S. grid (216, 3)
// ---------------------------------------------------------------------------
__global__ __launch_bounds__(256, 1) void qkv_mma_kernel(
    const float* __restrict__ temp_emb, const float* __restrict__ sp_emb)
{
    const int mat = blockIdx.y;
    const int m0 = blockIdx.x * 128;

    float c[2][8][4];
    mma_body(g_xh, mat, m0, c);

    const int w = threadIdx.x >> 5, lane = threadIdx.x & 31;
    const int wm = w & 3, wn = w >> 2;
    uint32_t* dsth = (mat == 0) ? g_Qh : (mat == 1) ? g_Kh : g_Vh;
#pragma unroll
    for (int mt = 0; mt < 2; mt++) {
#pragma unroll
        for (int rh = 0; rh < 2; rh++) {
            const int n   = m0 + wm * 32 + mt * 16 + (lane >> 2) + rh * 8;
            const int t   = n / HW_;
            const int rem = n % HW_;
            int qidx = 0;
            if (mat == 0) {
                const int yq = rem / W_, xq = rem % W_;
                const int yc = min(max(yq, 2), H_ - 3);
                const int xc = min(max(xq, 2), W_ - 3);
                qidx = (yq - yc + 2) * 5 + (xq - xc + 2);
            }
#pragma unroll
            for (int nt = 0; nt < 8; nt++) {
                const int col = wn * 64 + nt * 8 + 2 * (lane & 3);
                float v0 = c[mt][nt][rh * 2 + 0];
                float v1 = c[mt][nt][rh * 2 + 1];
                if (mat <= 1) {
                    v0 += temp_emb[t * CK + col];
                    v1 += temp_emb[t * CK + col + 1];
                }
                if (mat == 0) {
                    v0 = (v0 + sp_emb[qidx * CK + col]) * L2S;
                    v1 = (v1 + sp_emb[qidx * CK + col + 1]) * L2S;
                }
                dsth[(size_t)n * 64 + (col >> 1)] = h2pack(v0, v1);
            }
        }
    }
}

// ---------------------------------------------------------------------------
// Kernel: output projection via mma.sync + transposed writeout. grid 216
// ---------------------------------------------------------------------------
__global__ __launch_bounds__(256, 1) void outproj_mma_kernel(float* __restrict__ out)
{
    const int m0 = blockIdx.x * 128;

    float c[2][8][4];
    mma_body(g_Oh, 3, m0, c);

    const int w = threadIdx.x >> 5, lane = threadIdx.x & 31;
    const int wm = w & 3, wn = w >> 2;
#pragma unroll
    for (int mt = 0; mt < 2; mt++) {
#pragma unroll
        for (int rh = 0; rh < 2; rh++) {
            const int n   = m0 + wm * 32 + mt * 16 + (lane >> 2) + rh * 8;
            const int t   = n / HW_;
            const int rem = n % HW_;
            const size_t ob = (size_t)rem * (T_ * C_) + t * C_;
#pragma unroll
            for (int nt = 0; nt < 8; nt++) {
                const int col = wn * 64 + nt * 8 + 2 * (lane & 3);
                *(float2*)&out[ob + col] =
                    make_float2(c[mt][nt][rh * 2 + 0], c[mt][nt][rh * 2 + 1]);
            }
        }
    }
}

// ---------------------------------------------------------------------------
// Kernel: attention. 384 threads, 2 CTAs/SM. Each warp runs 2 (tq,h) items.
// ---------------------------------------------------------------------------
__global__ __launch_bounds__(384, 2) void attn_kernel()
{
    char* Krh = smraw;                       // 6 x SLICEB
    char* Vrh = smraw + 6 * SLICEB;          // 6 x SLICEB
    char* SPh = smraw + 12 * SLICEB;         // 25 x HROW

    const uint32_t sbase = (uint32_t)__cvta_generic_to_shared(smraw);
    const uint32_t Kb0 = sbase;
    const uint32_t Vb0 = sbase + 6 * SLICEB;
    const uint32_t SPb = sbase + 12 * SLICEB;

    const int x0  = blockIdx.x * QX;
    const int y0  = blockIdx.y * YSEG;
    const int tid = threadIdx.x;
    const int xbase = min(max(x0, 2), W_ - 3) - 2;

    // gather coords: 384 threads = 24 rows x 16 chunks; each does K and V
    const int grow = tid >> 4;
    const int gch  = tid & 15;
    const int gt   = grow >> 3;
    const int gcol = min(xbase + (grow & 7), W_ - 1);
    const size_t sgbase = (size_t)(gt * HW_ + gcol) * 64 + gch * 4;
    const uint32_t ssoff = (uint32_t)(grow * HROW + gch * 16);

    for (int i = tid; i < 400; i += 384) {
        int r = i >> 4, ch = i & 15;
        cp16(SPb + (uint32_t)(r * HROW + ch * 16), &g_sph[r * 64 + ch * 4]);
    }
    const int yc0 = min(max(y0, 2), H_ - 3);
#pragma unroll
    for (int r = 0; r < 5; r++) {
        const int yr = yc0 - 2 + r;
        const uint32_t so = (uint32_t)((yr % NSLOT) * SLICEB) + ssoff;
        const size_t g = sgbase + (size_t)yr * W_ * 64;
        cp16(Kb0 + so, &g_Kh[g]);
        cp16(Vb0 + so, &g_Vh[g]);
    }
    asm volatile("cp.async.commit_group;");
    asm volatile("cp.async.wait_group 0;");
    __syncthreads();
    int loaded_max = yc0 + 2;

    const int lane = tid & 31;
    const int w    = tid >> 5;           // 0..11

    const int qx  = lane >> 3;
    const int rl  = lane & 7;
    const int xoffq = min(max(x0 + qx, 2), W_ - 3) - 2 - xbase;
    const int kxr   = rl - xoffq;
    const bool valid = (kxr >= 0) && (kxr <= 4);
    const int kxrc  = min(max(kxr, 0), 4);

    for (int yq = y0; yq < y0 + YSEG; yq++) {
        const int yc = min(max(yq, 2), H_ - 3);

        const int need_next = min(max(yq + 1, 2), H_ - 3) + 2;
        const bool pf = (yq + 1 < y0 + YSEG) && (need_next > loaded_max);
        if (pf) {
            const uint32_t so = (uint32_t)((need_next % NSLOT) * SLICEB) + ssoff;
            const size_t g = sgbase + (size_t)need_next * W_ * 64;
            cp16(Kb0 + so, &g_Kh[g]);
            cp16(Vb0 + so, &g_Vh[g]);
            asm volatile("cp.async.commit_group;");
            loaded_max = need_next;
        }

        int slot[5];
        {
            int s0 = (yc - 2) % NSLOT;
#pragma unroll
            for (int i5 = 0; i5 < 5; i5++) {
                slot[i5] = s0;
                s0 = (s0 + 1 == NSLOT) ? 0 : s0 + 1;
            }
        }

#pragma unroll
        for (int item = 0; item < 2; item++) {
            const int wi = (w << 1) | item;   // 0..23
            const int tq = wi >> 3;
            const int h  = wi & 7;
            const int hb = h << 5;

            // Q: fp16, pre-scaled by L2S (2 x LDG.128)
            const uint4* qp = (const uint4*)&g_Qh[(size_t)(tq * HW_ + yq * W_ + x0 + qx) * 64 + (h << 3)];
            uint4 qa = qp[0], qb = qp[1];
            __half2 q2[8] = {H2(qa.x), H2(qa.y), H2(qa.z), H2(qa.w),
                             H2(qb.x), H2(qb.y), H2(qb.z), H2(qb.w)};

            // phase 1: Q.K
            float a[15];
#pragma unroll
            for (int tk = 0; tk < 3; tk++) {
#pragma unroll
                for (int i5 = 0; i5 < 5; i5++) {
                    const char* kr = Krh + slot[i5] * SLICEB + (tk * 8 + rl) * HROW + hb;
                    uint4 ka = *(const uint4*)kr;
                    uint4 kb = *(const uint4*)(kr + 16);
                    __half2 s2 = __hmul2(q2[0], H2(ka.x));
                    s2 = __hfma2(q2[1], H2(ka.y), s2);
                    s2 = __hfma2(q2[2], H2(ka.z), s2);
                    s2 = __hfma2(q2[3], H2(ka.w), s2);
                    s2 = __hfma2(q2[4], H2(kb.x), s2);
                    s2 = __hfma2(q2[5], H2(kb.y), s2);
                    s2 = __hfma2(q2[6], H2(kb.z), s2);
                    s2 = __hfma2(q2[7], H2(kb.w), s2);
                    float2 f = __half22float2(s2);
                    a[tk * 5 + i5] = f.x + f.y;
                }
            }

            float qsp[5];
#pragma unroll
            for (int i5 = 0; i5 < 5; i5++) {
                const char* sp = SPh + (i5 * 5 + kxrc) * HROW + hb;
                uint4 sa = *(const uint4*)sp;
                uint4 sb2 = *(const uint4*)(sp + 16);
                __half2 s2 = __hmul2(q2[0], H2(sa.x));
                s2 = __hfma2(q2[1], H2(sa.y), s2);
                s2 = __hfma2(q2[2], H2(sa.z), s2);
                s2 = __hfma2(q2[3], H2(sa.w), s2);
                s2 = __hfma2(q2[4], H2(sb2.x), s2);
                s2 = __hfma2(q2[5], H2(sb2.y), s2);
                s2 = __hfma2(q2[6], H2(sb2.z), s2);
                s2 = __hfma2(q2[7], H2(sb2.w), s2);
                float2 f = __half22float2(s2);
                qsp[i5] = f.x + f.y;
            }

            __half2 a2[15];
            float ssum = 0.f;
#pragma unroll
            for (int tk = 0; tk < 3; tk++)
#pragma unroll
                for (int i5 = 0; i5 < 5; i5++) {
                    int idx = tk * 5 + i5;
                    float e = ex2(a[idx] + qsp[i5]);   // Q pre-scaled
                    e = valid ? e : 0.f;
                    ssum += e;
                    a2[idx] = __floats2half2_rn(e, e);
                }
            ssum += __shfl_xor_sync(0xffffffffu, ssum, 1);
            ssum += __shfl_xor_sync(0xffffffffu, ssum, 2);
            ssum += __shfl_xor_sync(0xffffffffu, ssum, 4);
            float rs = __fdividef(1.f, ssum);

            // phase 2: AV, HFMA2 per tk group
            u64 facc[8];
#pragma unroll
            for (int i = 0; i < 8; i++) facc[i] = 0ull;

#pragma unroll
            for (int tk = 0; tk < 3; tk++) {
                __half2 hc[8];
#pragma unroll
                for (int i = 0; i < 8; i++) hc[i] = __floats2half2_rn(0.f, 0.f);
#pragma unroll
                for (int i5 = 0; i5 < 5; i5++) {
                    const char* vr = Vrh + slot[i5] * SLICEB + (tk * 8 + rl) * HROW + hb;
                    uint4 va = *(const uint4*)vr;
                    uint4 vb = *(const uint4*)(vr + 16);
                    __half2 aa = a2[tk * 5 + i5];
                    hc[0] = __hfma2(aa, H2(va.x), hc[0]);
                    hc[1] = __hfma2(aa, H2(va.y), hc[1]);
                    hc[2] = __hfma2(aa, H2(va.z), hc[2]);
                    hc[3] = __hfma2(aa, H2(va.w), hc[3]);
                    hc[4] = __hfma2(aa, H2(vb.x), hc[4]);
                    hc[5] = __hfma2(aa, H2(vb.y), hc[5]);
                    hc[6] = __hfma2(aa, H2(vb.z), hc[6]);
                    hc[7] = __hfma2(aa, H2(vb.w), hc[7]);
                }
#pragma unroll
                for (int i = 0; i < 8; i++) {
                    float2 f = __half22float2(hc[i]);
                    facc[i] = fadd2(facc[i], pack2(f.x, f.y));
                }
            }
#pragma unroll
            for (int off = 1; off <= 4; off <<= 1)
#pragma unroll
                for (int i = 0; i < 8; i++)
                    facc[i] = fadd2(facc[i], __shfl_xor_sync(0xffffffffu, facc[i], off));

            u64 m0v = (rl & 1) ? facc[1] : facc[0];
            u64 m1v = (rl & 1) ? facc[3] : facc[2];
            u64 m2v = (rl & 1) ? facc[5] : facc[4];
            u64 m3v = (rl & 1) ? facc[7] : facc[6];
            u64 n0v = (rl & 2) ? m1v : m0v;
            u64 n1v = (rl & 2) ? m3v : m2v;
            u64 sv  = (rl & 4) ? n1v : n0v;
            sv = fmul2(sv, pack2(rs, rs));
            float2 pv = unpack2(sv);
            const int n = tq * HW_ + yq * W_ + x0 + qx;
            g_Oh[(size_t)n * 64 + (h << 3) + rl] = h2pack(pv.x, pv.y);
        }

        if (pf) asm volatile("cp.async.wait_group 0;");
        __syncthreads();
    }
}

// ---------------------------------------------------------------------------
extern "C" void kernel_launch(void* const* d_in, const int* in_sizes, int n_in,
                              void* d_out, int out_size)
{
    const float* x    = (const float*)d_in[0];
    const float* Wq   = (const float*)d_in[1];
    const float* Wk   = (const float*)d_in[2];
    const float* Wv   = (const float*)d_in[3];
    const float* Wo   = (const float*)d_in[4];
    const float* temp = (const float*)d_in[5];
    const float* sp   = (const float*)d_in[6];
    float* out = (float*)d_out;

    cudaFuncSetAttribute(qkv_mma_kernel, cudaFuncAttributeMaxDynamicSharedMemorySize, GEMM_SMEM);
    cudaFuncSetAttribute(outproj_mma_kernel, cudaFuncAttributeMaxDynamicSharedMemorySize, GEMM_SMEM);
    cudaFuncSetAttribute(attn_kernel, cudaFuncAttributeMaxDynamicSharedMemorySize, ATTN_SMEM);

    prep_kernel<<<NXB + 5, 256>>>(x, Wq, Wk, Wv, Wo, sp);
    qkv_mma_kernel<<<dim3(NT / 128, 3), 256, GEMM_SMEM>>>(temp, sp);

    attn_kernel<<<dim3(XS, YB), 384, ATTN_SMEM>>>();

    outproj_mma_kernel<<<NT / 128, 256, GEMM_SMEM>>>(out);
}

// round 16
// speedup vs baseline: 1.1749x; 1.0549x over previous
#include <cuda_runtime.h>
#include <cuda_fp16.h>
#include <cstdint>

#define T_  3
#define H_  96
#define W_  96
#define C_  128
#define CK  128
#define NHEAD 8
#define DH  16
#define HW_ (H_*W_)
#define NT  (T_*HW_)        // 27648
#define QX  4
#define YSEG 8              // y rows per block (2 CTAs/SM attention)
#define XS (W_/QX)          // 24
#define YB (H_/YSEG)        // 12
#define NSLOT 6

// fp16 K/V smem layout: row = 128 halves = 256B data + 16B pad
#define HROW 272
#define SLICEB (24*HROW)
#define ATTN_SMEM (12*SLICEB + 25*HROW)   // 85136

typedef unsigned long long u64;

extern __shared__ char smraw[];

// fp16 packed pairs (half2 per uint32): 64 per row of 128
__device__ uint32_t g_Qh[NT*64], g_Kh[NT*64], g_Vh[NT*64], g_Oh[NT*64];
__device__ uint32_t g_sph[25*64];
__device__ uint32_t g_xh[NT*64];
__device__ uint32_t g_Whh[4][128*64], g_Whl[4][128*64];   // [k][n-pairs], fp16 hi/lo

// ---------------- helpers ----------------
__device__ __forceinline__ u64 fadd2(u64 a, u64 b) {
    u64 d; asm("add.rn.f32x2 %0,%1,%2;" : "=l"(d) : "l"(a), "l"(b)); return d;
}
__device__ __forceinline__ u64 fmul2(u64 a, u64 b) {
    u64 d; asm("mul.rn.f32x2 %0,%1,%2;" : "=l"(d) : "l"(a), "l"(b)); return d;
}
__device__ __forceinline__ u64 pack2(float lo, float hi) {
    u64 d; asm("mov.b64 %0,{%1,%2};" : "=l"(d) : "f"(lo), "f"(hi)); return d;
}
__device__ __forceinline__ float2 unpack2(u64 v) {
    float2 r; asm("mov.b64 {%0,%1},%2;" : "=f"(r.x), "=f"(r.y) : "l"(v)); return r;
}
__device__ __forceinline__ void cp16(uint32_t dst, const void* src) {
    asm volatile("cp.async.cg.shared.global [%0], [%1], 16;" :: "r"(dst), "l"(src));
}
__device__ __forceinline__ float ex2(float t) {
    float e; asm("ex2.approx.f32 %0, %1;" : "=f"(e) : "f"(t)); return e;
}
__device__ __forceinline__ uint32_t h2pack(float x0, float x1) {
    __half2 h = __float22half2_rn(make_float2(x0, x1));
    return *reinterpret_cast<uint32_t*>(&h);
}
#define H2(u) (*reinterpret_cast<const __half2*>(&(u)))

// ---------------- mma helpers ----------------
__device__ __forceinline__ void ldsm_x4(uint32_t* a, uint32_t addr) {
    asm volatile("ldmatrix.sync.aligned.m8n8.x4.shared.b16 {%0,%1,%2,%3}, [%4];"
                 : "=r"(a[0]), "=r"(a[1]), "=r"(a[2]), "=r"(a[3]) : "r"(addr));
}
__device__ __forceinline__ void ldsm_x2t(uint32_t* b, uint32_t addr) {
    asm volatile("ldmatrix.sync.aligned.m8n8.x2.trans.shared.b16 {%0,%1}, [%2];"
                 : "=r"(b[0]), "=r"(b[1]) : "r"(addr));
}
__device__ __forceinline__ void mma16816(float* c, const uint32_t* a, const uint32_t* b) {
    asm volatile(
        "mma.sync.aligned.m16n8k16.row.col.f32.f16.f16.f32 "
        "{%0,%1,%2,%3}, {%4,%5,%6,%7}, {%8,%9}, {%0,%1,%2,%3};"
        : "+f"(c[0]), "+f"(c[1]), "+f"(c[2]), "+f"(c[3])
        : "r"(a[0]), "r"(a[1]), "r"(a[2]), "r"(a[3]), "r"(b[0]), "r"(b[1]));
}

#define BROW 272
#define TILE_B (128*BROW)
#define A_OFF  0
#define BH_OFF TILE_B
#define BL_OFF (2*TILE_B)
#define GEMM_SMEM (3*TILE_B)    // 104448

#define L2S 0.36067376022224085f   // 0.25 * log2(e)

// ---------------------------------------------------------------------------
// prep kernel: blocks [0, NXB) do x conversion; blocks [NXB, NXB+5) do W/sp.
// ---------------------------------------------------------------------------
#define NXB (NT*32/256)
__global__ __launch_bounds__(256) void prep_kernel(
    const float* __restrict__ x,
    const float* __restrict__ Wq, const float* __restrict__ Wk,
    const float* __restrict__ Wv, const float* __restrict__ Wo,
    const float* __restrict__ sp_emb)
{
    const int b = blockIdx.x;
    if (b < NXB) {
        int i = b * 256 + threadIdx.x;
        float4 v = *(const float4*)&x[(size_t)i * 4];
        *(uint2*)&g_xh[i * 2] = make_uint2(h2pack(v.x, v.y), h2pack(v.z, v.w));
        return;
    }
    const int mat = b - NXB;
    if (mat == 4) {
        for (int i = threadIdx.x; i < 25 * 64; i += 256) {
            float2 v = *(const float2*)&sp_emb[(size_t)i * 2];
            g_sph[i] = h2pack(v.x, v.y);
        }
        return;
    }
    const float* Wsrc = (mat == 0) ? Wq : (mat == 1) ? Wk : (mat == 2) ? Wv : Wo;
    for (int p = threadIdx.x; p < 128 * 64; p += 256) {
        float2 v = *(const float2*)&Wsrc[(size_t)p * 2];
        __half h0 = __float2half_rn(v.x);
        __half h1 = __float2half_rn(v.y);
        __half l0 = __float2half_rn(v.x - __half2float(h0));
        __half l1 = __float2half_rn(v.y - __half2float(h1));
        g_Whh[mat][p] = ((uint32_t)__half_as_ushort(h1) << 16) | __half_as_ushort(h0);
        g_Whl[mat][p] = ((uint32_t)__half_as_ushort(l1) << 16) | __half_as_ushort(l0);
    }
}

// ---------------------------------------------------------------------------
// Shared MMA body: fp16 2-pass (A*Bh + A*Bl). c[2][8][4] per warp.
// ---------------------------------------------------------------------------
__device__ __forceinline__ void mma_body(
    const uint32_t* __restrict__ A, int mat, int m0, float c[2][8][4])
{
    const int tid  = threadIdx.x;
    const int w    = tid >> 5;
    const int lane = tid & 31;
    const uint32_t sb = (uint32_t)__cvta_generic_to_shared(smraw);

#pragma unroll
    for (int it = 0; it < 8; it++) {
        int i = tid + it * 256;
        int r = i >> 4, ch = i & 15;
        uint32_t d = (uint32_t)(r * BROW + ch * 16);
        cp16(sb + A_OFF + d, (const char*)A + ((size_t)(m0 + r) * 64 + ch * 4) * 4);
        cp16(sb + BH_OFF + d, (const char*)&g_Whh[mat][r * 64 + ch * 4]);
    }
    asm volatile("cp.async.commit_group;");
#pragma unroll
    for (int it = 0; it < 8; it++) {
        int i = tid + it * 256;
        int r = i >> 4, ch = i & 15;
        uint32_t d = (uint32_t)(r * BROW + ch * 16);
        cp16(sb + BL_OFF + d, (const char*)&g_Whl[mat][r * 64 + ch * 4]);
    }
    asm volatile("cp.async.commit_group;");

#pragma unroll
    for (int mt = 0; mt < 2; mt++)
#pragma unroll
        for (int nt = 0; nt < 8; nt++)
#pragma unroll
            for (int j = 0; j < 4; j++) c[mt][nt][j] = 0.f;

    const int wm = w & 3, wn = w >> 2;
    const uint32_t aBase = sb + A_OFF + (uint32_t)((wm * 32 + (lane & 15)) * BROW + (lane >> 4) * 16);
    const uint32_t bBase = sb + (uint32_t)((lane & 15) * BROW + wn * 128);
    const uint32_t bOffP[2] = {BH_OFF, BL_OFF};

    asm volatile("cp.async.wait_group 1;");
    __syncthreads();

#pragma unroll
    for (int pass = 0; pass < 2; pass++) {
        if (pass == 1) {
            asm volatile("cp.async.wait_group 0;");
            __syncthreads();
        }
        const uint32_t bT = bBase + bOffP[pass];
#pragma unroll
        for (int k8 = 0; k8 < 8; k8++) {
            uint32_t a[2][4], b[8][2];
#pragma unroll
            for (int mt = 0; mt < 2; mt++)
                ldsm_x4(a[mt], aBase + (uint32_t)(mt * 16 * BROW + k8 * 32));
#pragma unroll
            for (int nt = 0; nt < 8; nt++)
                ldsm_x2t(b[nt], bT + (uint32_t)(k8 * 16 * BROW + nt * 16));
#pragma unroll
            for (int mt = 0; mt < 2; mt++)
#pragma unroll
                for (int nt = 0; nt < 8; nt++)
                    mma16816(c[mt][nt], a[mt], b[nt]);
        }
    }
}

// ---------------------------------------------------------------------------
// Kernel: QKV via mma.sync. Q pre-scaled by L2S. grid (216, 3). 2 CTAs/SM.
// ---------------------------------------------------------------------------
__global__ __launch_bounds__(256, 2) void qkv_mma_kernel(
    const float* __restrict__ temp_emb, const float* __restrict__ sp_emb)
{
    const int mat = blockIdx.y;
    const int m0 = blockIdx.x * 128;

    float c[2][8][4];
    mma_body(g_xh, mat, m0, c);

    const int w = threadIdx.x >> 5, lane = threadIdx.x & 31;
    const int wm = w & 3, wn = w >> 2;
    uint32_t* dsth = (mat == 0) ? g_Qh : (mat == 1) ? g_Kh : g_Vh;
#pragma unroll
    for (int mt = 0; mt < 2; mt++) {
#pragma unroll
        for (int rh = 0; rh < 2; rh++) {
            const int n   = m0 + wm * 32 + mt * 16 + (lane >> 2) + rh * 8;
            const int t   = n / HW_;
            const int rem = n % HW_;
            int qidx = 0;
            if (mat == 0) {
                const int yq = rem / W_, xq = rem % W_;
                const int yc = min(max(yq, 2), H_ - 3);
                const int xc = min(max(xq, 2), W_ - 3);
                qidx = (yq - yc + 2) * 5 + (xq - xc + 2);
            }
#pragma unroll
            for (int nt = 0; nt < 8; nt++) {
                const int col = wn * 64 + nt * 8 + 2 * (lane & 3);
                float v0 = c[mt][nt][rh * 2 + 0];
                float v1 = c[mt][nt][rh * 2 + 1];
                if (mat <= 1) {
                    v0 += temp_emb[t * CK + col];
                    v1 += temp_emb[t * CK + col + 1];
                }
                if (mat == 0) {
                    v0 = (v0 + sp_emb[qidx * CK + col]) * L2S;
                    v1 = (v1 + sp_emb[qidx * CK + col + 1]) * L2S;
                }
                dsth[(size_t)n * 64 + (col >> 1)] = h2pack(v0, v1);
            }
        }
    }
}

// ---------------------------------------------------------------------------
// Kernel: output projection. grid 216. 2 CTAs/SM.
// ---------------------------------------------------------------------------
__global__ __launch_bounds__(256, 2) void outproj_mma_kernel(float* __restrict__ out)
{
    const int m0 = blockIdx.x * 128;

    float c[2][8][4];
    mma_body(g_Oh, 3, m0, c);

    const int w = threadIdx.x >> 5, lane = threadIdx.x & 31;
    const int wm = w & 3, wn = w >> 2;
#pragma unroll
    for (int mt = 0; mt < 2; mt++) {
#pragma unroll
        for (int rh = 0; rh < 2; rh++) {
            const int n   = m0 + wm * 32 + mt * 16 + (lane >> 2) + rh * 8;
            const int t   = n / HW_;
            const int rem = n % HW_;
            const size_t ob = (size_t)rem * (T_ * C_) + t * C_;
#pragma unroll
            for (int nt = 0; nt < 8; nt++) {
                const int col = wn * 64 + nt * 8 + 2 * (lane & 3);
                *(float2*)&out[ob + col] =
                    make_float2(c[mt][nt][rh * 2 + 0], c[mt][nt][rh * 2 + 1]);
            }
        }
    }
}

// ---------------------------------------------------------------------------
// Kernel: attention. 384 threads, 2 CTAs/SM. Each warp runs 2 (tq,h) items.
// ---------------------------------------------------------------------------
__global__ __launch_bounds__(384, 2) void attn_kernel()
{
    char* Krh = smraw;                       // 6 x SLICEB
    char* Vrh = smraw + 6 * SLICEB;          // 6 x SLICEB
    char* SPh = smraw + 12 * SLICEB;         // 25 x HROW

    const uint32_t sbase = (uint32_t)__cvta_generic_to_shared(smraw);
    const uint32_t Kb0 = sbase;
    const uint32_t Vb0 = sbase + 6 * SLICEB;
    const uint32_t SPb = sbase + 12 * SLICEB;

    const int x0  = blockIdx.x * QX;
    const int y0  = blockIdx.y * YSEG;
    const int tid = threadIdx.x;
    const int xbase = min(max(x0, 2), W_ - 3) - 2;

    const int grow = tid >> 4;
    const int gch  = tid & 15;
    const int gt   = grow >> 3;
    const int gcol = min(xbase + (grow & 7), W_ - 1);
    const size_t sgbase = (size_t)(gt * HW_ + gcol) * 64 + gch * 4;
    const uint32_t ssoff = (uint32_t)(grow * HROW + gch * 16);

    for (int i = tid; i < 400; i += 384) {
        int r = i >> 4, ch = i & 15;
        cp16(SPb + (uint32_t)(r * HROW + ch * 16), &g_sph[r * 64 + ch * 4]);
    }
    const int yc0 = min(max(y0, 2), H_ - 3);
#pragma unroll
    for (int r = 0; r < 5; r++) {
        const int yr = yc0 - 2 + r;
        const uint32_t so = (uint32_t)((yr % NSLOT) * SLICEB) + ssoff;
        const size_t g = sgbase + (size_t)yr * W_ * 64;
        cp16(Kb0 + so, &g_Kh[g]);
        cp16(Vb0 + so, &g_Vh[g]);
    }
    asm volatile("cp.async.commit_group;");
    asm volatile("cp.async.wait_group 0;");
    __syncthreads();
    int loaded_max = yc0 + 2;

    const int lane = tid & 31;
    const int w    = tid >> 5;           // 0..11

    const int qx  = lane >> 3;
    const int rl  = lane & 7;
    const int xoffq = min(max(x0 + qx, 2), W_ - 3) - 2 - xbase;
    const int kxr   = rl - xoffq;
    const bool valid = (kxr >= 0) && (kxr <= 4);
    const int kxrc  = min(max(kxr, 0), 4);

    for (int yq = y0; yq < y0 + YSEG; yq++) {
        const int yc = min(max(yq, 2), H_ - 3);

        const int need_next = min(max(yq + 1, 2), H_ - 3) + 2;
        const bool pf = (yq + 1 < y0 + YSEG) && (need_next > loaded_max);
        if (pf) {
            const uint32_t so = (uint32_t)((need_next % NSLOT) * SLICEB) + ssoff;
            const size_t g = sgbase + (size_t)need_next * W_ * 64;
            cp16(Kb0 + so, &g_Kh[g]);
            cp16(Vb0 + so, &g_Vh[g]);
            asm volatile("cp.async.commit_group;");
            loaded_max = need_next;
        }

        int slot[5];
        {
            int s0 = (yc - 2) % NSLOT;
#pragma unroll
            for (int i5 = 0; i5 < 5; i5++) {
                slot[i5] = s0;
                s0 = (s0 + 1 == NSLOT) ? 0 : s0 + 1;
            }
        }

#pragma unroll
        for (int item = 0; item < 2; item++) {
            const int wi = (w << 1) | item;   // 0..23
            const int tq = wi >> 3;
            const int h  = wi & 7;
            const int hb = h << 5;

            const uint4* qp = (const uint4*)&g_Qh[(size_t)(tq * HW_ + yq * W_ + x0 + qx) * 64 + (h << 3)];
            uint4 qa = qp[0], qb = qp[1];
            __half2 q2[8] = {H2(qa.x), H2(qa.y), H2(qa.z), H2(qa.w),
                             H2(qb.x), H2(qb.y), H2(qb.z), H2(qb.w)};

            float a[15];
#pragma unroll
            for (int tk = 0; tk < 3; tk++) {
#pragma unroll
                for (int i5 = 0; i5 < 5; i5++) {
                    const char* kr = Krh + slot[i5] * SLICEB + (tk * 8 + rl) * HROW + hb;
                    uint4 ka = *(const uint4*)kr;
                    uint4 kb = *(const uint4*)(kr + 16);
                    __half2 s2 = __hmul2(q2[0], H2(ka.x));
                    s2 = __hfma2(q2[1], H2(ka.y), s2);
                    s2 = __hfma2(q2[2], H2(ka.z), s2);
                    s2 = __hfma2(q2[3], H2(ka.w), s2);
                    s2 = __hfma2(q2[4], H2(kb.x), s2);
                    s2 = __hfma2(q2[5], H2(kb.y), s2);
                    s2 = __hfma2(q2[6], H2(kb.z), s2);
                    s2 = __hfma2(q2[7], H2(kb.w), s2);
                    float2 f = __half22float2(s2);
                    a[tk * 5 + i5] = f.x + f.y;
                }
            }

            float qsp[5];
#pragma unroll
            for (int i5 = 0; i5 < 5; i5++) {
                const char* sp = SPh + (i5 * 5 + kxrc) * HROW + hb;
                uint4 sa = *(const uint4*)sp;
                uint4 sb2 = *(const uint4*)(sp + 16);
                __half2 s2 = __hmul2(q2[0], H2(sa.x));
                s2 = __hfma2(q2[1], H2(sa.y), s2);
                s2 = __hfma2(q2[2], H2(sa.z), s2);
                s2 = __hfma2(q2[3], H2(sa.w), s2);
                s2 = __hfma2(q2[4], H2(sb2.x), s2);
                s2 = __hfma2(q2[5], H2(sb2.y), s2);
                s2 = __hfma2(q2[6], H2(sb2.z), s2);
                s2 = __hfma2(q2[7], H2(sb2.w), s2);
                float2 f = __half22float2(s2);
                qsp[i5] = f.x + f.y;
            }

            __half2 a2[15];
            float ssum = 0.f;
#pragma unroll
            for (int tk = 0; tk < 3; tk++)
#pragma unroll
                for (int i5 = 0; i5 < 5; i5++) {
                    int idx = tk * 5 + i5;
                    float e = ex2(a[idx] + qsp[i5]);   // Q pre-scaled
                    e = valid ? e : 0.f;
                    ssum += e;
                    a2[idx] = __floats2half2_rn(e, e);
                }
            ssum += __shfl_xor_sync(0xffffffffu, ssum, 1);
            ssum += __shfl_xor_sync(0xffffffffu, ssum, 2);
            ssum += __shfl_xor_sync(0xffffffffu, ssum, 4);
            float rs = __fdividef(1.f, ssum);

            u64 facc[8];
#pragma unroll
            for (int i = 0; i < 8; i++) facc[i] = 0ull;

#pragma unroll
            for (int tk = 0; tk < 3; tk++) {
                __half2 hc[8];
#pragma unroll
                for (int i = 0; i < 8; i++) hc[i] = __floats2half2_rn(0.f, 0.f);
#pragma unroll
                for (int i5 = 0; i5 < 5; i5++) {
                    const char* vr = Vrh + slot[i5] * SLICEB + (tk * 8 + rl) * HROW + hb;
                    uint4 va = *(const uint4*)vr;
                    uint4 vb = *(const uint4*)(vr + 16);
                    __half2 aa = a2[tk * 5 + i5];
                    hc[0] = __hfma2(aa, H2(va.x), hc[0]);
                    hc[1] = __hfma2(aa, H2(va.y), hc[1]);
                    hc[2] = __hfma2(aa, H2(va.z), hc[2]);
                    hc[3] = __hfma2(aa, H2(va.w), hc[3]);
                    hc[4] = __hfma2(aa, H2(vb.x), hc[4]);
                    hc[5] = __hfma2(aa, H2(vb.y), hc[5]);
                    hc[6] = __hfma2(aa, H2(vb.z), hc[6]);
                    hc[7] = __hfma2(aa, H2(vb.w), hc[7]);
                }
#pragma unroll
                for (int i = 0; i < 8; i++) {
                    float2 f = __half22float2(hc[i]);
                    facc[i] = fadd2(facc[i], pack2(f.x, f.y));
                }
            }
#pragma unroll
            for (int off = 1; off <= 4; off <<= 1)
#pragma unroll
                for (int i = 0; i < 8; i++)
                    facc[i] = fadd2(facc[i], __shfl_xor_sync(0xffffffffu, facc[i], off));

            u64 m0v = (rl & 1) ? facc[1] : facc[0];
            u64 m1v = (rl & 1) ? facc[3] : facc[2];
            u64 m2v = (rl & 1) ? facc[5] : facc[4];
            u64 m3v = (rl & 1) ? facc[7] : facc[6];
            u64 n0v = (rl & 2) ? m1v : m0v;
            u64 n1v = (rl & 2) ? m3v : m2v;
            u64 sv  = (rl & 4) ? n1v : n0v;
            sv = fmul2(sv, pack2(rs, rs));
            float2 pv = unpack2(sv);
            const int n = tq * HW_ + yq * W_ + x0 + qx;
            g_Oh[(size_t)n * 64 + (h << 3) + rl] = h2pack(pv.x, pv.y);
        }

        if (pf) asm volatile("cp.async.wait_group 0;");
        __syncthreads();
    }
}

// ---------------------------------------------------------------------------
extern "C" void kernel_launch(void* const* d_in, const int* in_sizes, int n_in,
                              void* d_out, int out_size)
{
    const float* x    = (const float*)d_in[0];
    const float* Wq   = (const float*)d_in[1];
    const float* Wk   = (const float*)d_in[2];
    const float* Wv   = (const float*)d_in[3];
    const float* Wo   = (const float*)d_in[4];
    const float* temp = (const float*)d_in[5];
    const float* sp   = (const float*)d_in[6];
    float* out = (float*)d_out;

    cudaFuncSetAttribute(qkv_mma_kernel, cudaFuncAttributeMaxDynamicSharedMemorySize, GEMM_SMEM);
    cudaFuncSetAttribute(outproj_mma_kernel, cudaFuncAttributeMaxDynamicSharedMemorySize, GEMM_SMEM);
    cudaFuncSetAttribute(attn_kernel, cudaFuncAttributeMaxDynamicSharedMemorySize, ATTN_SMEM);

    prep_kernel<<<NXB + 5, 256>>>(x, Wq, Wk, Wv, Wo, sp);
    qkv_mma_kernel<<<dim3(NT / 128, 3), 256, GEMM_SMEM>>>(temp, sp);

    attn_kernel<<<dim3(XS, YB), 384, ATTN_SMEM>>>();

    outproj_mma_kernel<<<NT / 128, 256, GEMM_SMEM>>>(out);
}

// round 17
// speedup vs baseline: 1.2950x; 1.1023x over previous
#include <cuda_runtime.h>
#include <cuda_fp16.h>
#include <cstdint>

#define T_  3
#define H_  96
#define W_  96
#define C_  128
#define CK  128
#define NHEAD 8
#define DH  16
#define HW_ (H_*W_)
#define NT  (T_*HW_)        // 27648
#define QX  4
#define YSEG 8              // y rows per block (2 CTAs/SM attention)
#define XS (W_/QX)          // 24
#define YB (H_/YSEG)        // 12
#define NSLOT 6

// fp16 K/V smem layout: row = 128 halves = 256B data + 16B pad
#define HROW 272
#define SLICEB (24*HROW)
#define ATTN_SMEM (12*SLICEB + 25*HROW)   // 85136

typedef unsigned long long u64;

extern __shared__ char smraw[];

// fp16 packed pairs (half2 per uint32): 64 per row of 128
__device__ uint32_t g_Qh[NT*64], g_Kh[NT*64], g_Vh[NT*64], g_Oh[NT*64];
__device__ uint32_t g_sph[25*64];
__device__ uint32_t g_xh[NT*64];
__device__ uint32_t g_Whh[4][128*64];   // [k][n-pairs], fp16

// ---------------- helpers ----------------
__device__ __forceinline__ u64 fadd2(u64 a, u64 b) {
    u64 d; asm("add.rn.f32x2 %0,%1,%2;" : "=l"(d) : "l"(a), "l"(b)); return d;
}
__device__ __forceinline__ u64 fmul2(u64 a, u64 b) {
    u64 d; asm("mul.rn.f32x2 %0,%1,%2;" : "=l"(d) : "l"(a), "l"(b)); return d;
}
__device__ __forceinline__ u64 pack2(float lo, float hi) {
    u64 d; asm("mov.b64 %0,{%1,%2};" : "=l"(d) : "f"(lo), "f"(hi)); return d;
}
__device__ __forceinline__ float2 unpack2(u64 v) {
    float2 r; asm("mov.b64 {%0,%1},%2;" : "=f"(r.x), "=f"(r.y) : "l"(v)); return r;
}
__device__ __forceinline__ void cp16(uint32_t dst, const void* src) {
    asm volatile("cp.async.cg.shared.global [%0], [%1], 16;" :: "r"(dst), "l"(src));
}
__device__ __forceinline__ float ex2(float t) {
    float e; asm("ex2.approx.f32 %0, %1;" : "=f"(e) : "f"(t)); return e;
}
__device__ __forceinline__ uint32_t h2pack(float x0, float x1) {
    __half2 h = __float22half2_rn(make_float2(x0, x1));
    return *reinterpret_cast<uint32_t*>(&h);
}
#define H2(u) (*reinterpret_cast<const __half2*>(&(u)))

// ---------------- mma helpers ----------------
__device__ __forceinline__ void ldsm_x4(uint32_t* a, uint32_t addr) {
    asm volatile("ldmatrix.sync.aligned.m8n8.x4.shared.b16 {%0,%1,%2,%3}, [%4];"
                 : "=r"(a[0]), "=r"(a[1]), "=r"(a[2]), "=r"(a[3]) : "r"(addr));
}
__device__ __forceinline__ void ldsm_x2t(uint32_t* b, uint32_t addr) {
    asm volatile("ldmatrix.sync.aligned.m8n8.x2.trans.shared.b16 {%0,%1}, [%2];"
                 : "=r"(b[0]), "=r"(b[1]) : "r"(addr));
}
__device__ __forceinline__ void mma16816(float* c, const uint32_t* a, const uint32_t* b) {
    asm volatile(
        "mma.sync.aligned.m16n8k16.row.col.f32.f16.f16.f32 "
        "{%0,%1,%2,%3}, {%4,%5,%6,%7}, {%8,%9}, {%0,%1,%2,%3};"
        : "+f"(c[0]), "+f"(c[1]), "+f"(c[2]), "+f"(c[3])
        : "r"(a[0]), "r"(a[1]), "r"(a[2]), "r"(a[3]), "r"(b[0]), "r"(b[1]));
}

#define BROW 272
#define TILE_B (128*BROW)
#define A_OFF  0
#define BH_OFF TILE_B
#define GEMM_SMEM (2*TILE_B)    // 69632

#define L2S 0.36067376022224085f   // 0.25 * log2(e)

// ---------------------------------------------------------------------------
// prep kernel: blocks [0, NXB) do x conversion; blocks [NXB, NXB+5) do W/sp.
// ---------------------------------------------------------------------------
#define NXB (NT*32/256)
__global__ __launch_bounds__(256) void prep_kernel(
    const float* __restrict__ x,
    const float* __restrict__ Wq, const float* __restrict__ Wk,
    const float* __restrict__ Wv, const float* __restrict__ Wo,
    const float* __restrict__ sp_emb)
{
    const int b = blockIdx.x;
    if (b < NXB) {
        int i = b * 256 + threadIdx.x;
        float4 v = *(const float4*)&x[(size_t)i * 4];
        *(uint2*)&g_xh[i * 2] = make_uint2(h2pack(v.x, v.y), h2pack(v.z, v.w));
        return;
    }
    const int mat = b - NXB;
    if (mat == 4) {
        for (int i = threadIdx.x; i < 25 * 64; i += 256) {
            float2 v = *(const float2*)&sp_emb[(size_t)i * 2];
            g_sph[i] = h2pack(v.x, v.y);
        }
        return;
    }
    const float* Wsrc = (mat == 0) ? Wq : (mat == 1) ? Wk : (mat == 2) ? Wv : Wo;
    for (int p = threadIdx.x; p < 128 * 64; p += 256) {
        float2 v = *(const float2*)&Wsrc[(size_t)p * 2];
        g_Whh[mat][p] = h2pack(v.x, v.y);
    }
}

// ---------------------------------------------------------------------------
// Shared MMA body: single-pass fp16 (A*B). c[2][8][4] per warp.
// ---------------------------------------------------------------------------
__device__ __forceinline__ void mma_body(
    const uint32_t* __restrict__ A, int mat, int m0, float c[2][8][4])
{
    const int tid  = threadIdx.x;
    const int w    = tid >> 5;
    const int lane = tid & 31;
    const uint32_t sb = (uint32_t)__cvta_generic_to_shared(smraw);

#pragma unroll
    for (int it = 0; it < 8; it++) {
        int i = tid + it * 256;
        int r = i >> 4, ch = i & 15;
        uint32_t d = (uint32_t)(r * BROW + ch * 16);
        cp16(sb + A_OFF + d, (const char*)A + ((size_t)(m0 + r) * 64 + ch * 4) * 4);
        cp16(sb + BH_OFF + d, (const char*)&g_Whh[mat][r * 64 + ch * 4]);
    }
    asm volatile("cp.async.commit_group;");

#pragma unroll
    for (int mt = 0; mt < 2; mt++)
#pragma unroll
        for (int nt = 0; nt < 8; nt++)
#pragma unroll
            for (int j = 0; j < 4; j++) c[mt][nt][j] = 0.f;

    const int wm = w & 3, wn = w >> 2;
    const uint32_t aBase = sb + A_OFF + (uint32_t)((wm * 32 + (lane & 15)) * BROW + (lane >> 4) * 16);
    const uint32_t bBase = sb + BH_OFF + (uint32_t)((lane & 15) * BROW + wn * 128);

    asm volatile("cp.async.wait_group 0;");
    __syncthreads();

#pragma unroll
    for (int k8 = 0; k8 < 8; k8++) {
        uint32_t a[2][4], b[8][2];
#pragma unroll
        for (int mt = 0; mt < 2; mt++)
            ldsm_x4(a[mt], aBase + (uint32_t)(mt * 16 * BROW + k8 * 32));
#pragma unroll
        for (int nt = 0; nt < 8; nt++)
            ldsm_x2t(b[nt], bBase + (uint32_t)(k8 * 16 * BROW + nt * 16));
#pragma unroll
        for (int mt = 0; mt < 2; mt++)
#pragma unroll
            for (int nt = 0; nt < 8; nt++)
                mma16816(c[mt][nt], a[mt], b[nt]);
    }
}

// ---------------------------------------------------------------------------
// Kernel: QKV via mma.sync. Q pre-scaled by L2S. grid (216, 3). 2 CTAs/SM.
// ---------------------------------------------------------------------------
__global__ __launch_bounds__(256, 2) void qkv_mma_kernel(
    const float* __restrict__ temp_emb, const float* __restrict__ sp_emb)
{
    const int mat = blockIdx.y;
    const int m0 = blockIdx.x * 128;

    float c[2][8][4];
    mma_body(g_xh, mat, m0, c);

    const int w = threadIdx.x >> 5, lane = threadIdx.x & 31;
    const int wm = w & 3, wn = w >> 2;
    uint32_t* dsth = (mat == 0) ? g_Qh : (mat == 1) ? g_Kh : g_Vh;
#pragma unroll
    for (int mt = 0; mt < 2; mt++) {
#pragma unroll
        for (int rh = 0; rh < 2; rh++) {
            const int n   = m0 + wm * 32 + mt * 16 + (lane >> 2) + rh * 8;
            const int t   = n / HW_;
            const int rem = n % HW_;
            int qidx = 0;
            if (mat == 0) {
                const int yq = rem / W_, xq = rem % W_;
                const int yc = min(max(yq, 2), H_ - 3);
                const int xc = min(max(xq, 2), W_ - 3);
                qidx = (yq - yc + 2) * 5 + (xq - xc + 2);
            }
#pragma unroll
            for (int nt = 0; nt < 8; nt++) {
                const int col = wn * 64 + nt * 8 + 2 * (lane & 3);
                float v0 = c[mt][nt][rh * 2 + 0];
                float v1 = c[mt][nt][rh * 2 + 1];
                if (mat <= 1) {
                    v0 += temp_emb[t * CK + col];
                    v1 += temp_emb[t * CK + col + 1];
                }
                if (mat == 0) {
                    v0 = (v0 + sp_emb[qidx * CK + col]) * L2S;
                    v1 = (v1 + sp_emb[qidx * CK + col + 1]) * L2S;
                }
                dsth[(size_t)n * 64 + (col >> 1)] = h2pack(v0, v1);
            }
        }
    }
}

// ---------------------------------------------------------------------------
// Kernel: output projection. grid 216. 2 CTAs/SM.
// ---------------------------------------------------------------------------
__global__ __launch_bounds__(256, 2) void outproj_mma_kernel(float* __restrict__ out)
{
    const int m0 = blockIdx.x * 128;

    float c[2][8][4];
    mma_body(g_Oh, 3, m0, c);

    const int w = threadIdx.x >> 5, lane = threadIdx.x & 31;
    const int wm = w & 3, wn = w >> 2;
#pragma unroll
    for (int mt = 0; mt < 2; mt++) {
#pragma unroll
        for (int rh = 0; rh < 2; rh++) {
            const int n   = m0 + wm * 32 + mt * 16 + (lane >> 2) + rh * 8;
            const int t   = n / HW_;
            const int rem = n % HW_;
            const size_t ob = (size_t)rem * (T_ * C_) + t * C_;
#pragma unroll
            for (int nt = 0; nt < 8; nt++) {
                const int col = wn * 64 + nt * 8 + 2 * (lane & 3);
                *(float2*)&out[ob + col] =
                    make_float2(c[mt][nt][rh * 2 + 0], c[mt][nt][rh * 2 + 1]);
            }
        }
    }
}

// ---------------------------------------------------------------------------
// Kernel: attention. 384 threads, 2 CTAs/SM. Each warp runs 2 (tq,h) items.
// ---------------------------------------------------------------------------
__global__ __launch_bounds__(384, 2) void attn_kernel()
{
    char* Krh = smraw;                       // 6 x SLICEB
    char* Vrh = smraw + 6 * SLICEB;          // 6 x SLICEB
    char* SPh = smraw + 12 * SLICEB;         // 25 x HROW

    const uint32_t sbase = (uint32_t)__cvta_generic_to_shared(smraw);
    const uint32_t Kb0 = sbase;
    const uint32_t Vb0 = sbase + 6 * SLICEB;
    const uint32_t SPb = sbase + 12 * SLICEB;

    const int x0  = blockIdx.x * QX;
    const int y0  = blockIdx.y * YSEG;
    const int tid = threadIdx.x;
    const int xbase = min(max(x0, 2), W_ - 3) - 2;

    const int grow = tid >> 4;
    const int gch  = tid & 15;
    const int gt   = grow >> 3;
    const int gcol = min(xbase + (grow & 7), W_ - 1);
    const size_t sgbase = (size_t)(gt * HW_ + gcol) * 64 + gch * 4;
    const uint32_t ssoff = (uint32_t)(grow * HROW + gch * 16);

    for (int i = tid; i < 400; i += 384) {
        int r = i >> 4, ch = i & 15;
        cp16(SPb + (uint32_t)(r * HROW + ch * 16), &g_sph[r * 64 + ch * 4]);
    }
    const int yc0 = min(max(y0, 2), H_ - 3);
#pragma unroll
    for (int r = 0; r < 5; r++) {
        const int yr = yc0 - 2 + r;
        const uint32_t so = (uint32_t)((yr % NSLOT) * SLICEB) + ssoff;
        const size_t g = sgbase + (size_t)yr * W_ * 64;
        cp16(Kb0 + so, &g_Kh[g]);
        cp16(Vb0 + so, &g_Vh[g]);
    }
    asm volatile("cp.async.commit_group;");
    asm volatile("cp.async.wait_group 0;");
    __syncthreads();
    int loaded_max = yc0 + 2;

    const int lane = tid & 31;
    const int w    = tid >> 5;           // 0..11

    const int qx  = lane >> 3;
    const int rl  = lane & 7;
    const int xoffq = min(max(x0 + qx, 2), W_ - 3) - 2 - xbase;
    const int kxr   = rl - xoffq;
    const bool valid = (kxr >= 0) && (kxr <= 4);
    const int kxrc  = min(max(kxr, 0), 4);

    for (int yq = y0; yq < y0 + YSEG; yq++) {
        const int yc = min(max(yq, 2), H_ - 3);

        const int need_next = min(max(yq + 1, 2), H_ - 3) + 2;
        const bool pf = (yq + 1 < y0 + YSEG) && (need_next > loaded_max);
        if (pf) {
            const uint32_t so = (uint32_t)((need_next % NSLOT) * SLICEB) + ssoff;
            const size_t g = sgbase + (size_t)need_next * W_ * 64;
            cp16(Kb0 + so, &g_Kh[g]);
            cp16(Vb0 + so, &g_Vh[g]);
            asm volatile("cp.async.commit_group;");
            loaded_max = need_next;
        }

        int slot[5];
        {
            int s0 = (yc - 2) % NSLOT;
#pragma unroll
            for (int i5 = 0; i5 < 5; i5++) {
                slot[i5] = s0;
                s0 = (s0 + 1 == NSLOT) ? 0 : s0 + 1;
            }
        }

#pragma unroll
        for (int item = 0; item < 2; item++) {
            const int wi = (w << 1) | item;   // 0..23
            const int tq = wi >> 3;
            const int h  = wi & 7;
            const int hb = h << 5;

            const uint4* qp = (const uint4*)&g_Qh[(size_t)(tq * HW_ + yq * W_ + x0 + qx) * 64 + (h << 3)];
            uint4 qa = qp[0], qb = qp[1];
            __half2 q2[8] = {H2(qa.x), H2(qa.y), H2(qa.z), H2(qa.w),
                             H2(qb.x), H2(qb.y), H2(qb.z), H2(qb.w)};

            float a[15];
#pragma unroll
            for (int tk = 0; tk < 3; tk++) {
#pragma unroll
                for (int i5 = 0; i5 < 5; i5++) {
                    const char* kr = Krh + slot[i5] * SLICEB + (tk * 8 + rl) * HROW + hb;
                    uint4 ka = *(const uint4*)kr;
                    uint4 kb = *(const uint4*)(kr + 16);
                    __half2 s2 = __hmul2(q2[0], H2(ka.x));
                    s2 = __hfma2(q2[1], H2(ka.y), s2);
                    s2 = __hfma2(q2[2], H2(ka.z), s2);
                    s2 = __hfma2(q2[3], H2(ka.w), s2);
                    s2 = __hfma2(q2[4], H2(kb.x), s2);
                    s2 = __hfma2(q2[5], H2(kb.y), s2);
                    s2 = __hfma2(q2[6], H2(kb.z), s2);
                    s2 = __hfma2(q2[7], H2(kb.w), s2);
                    float2 f = __half22float2(s2);
                    a[tk * 5 + i5] = f.x + f.y;
                }
            }

            float qsp[5];
#pragma unroll
            for (int i5 = 0; i5 < 5; i5++) {
                const char* sp = SPh + (i5 * 5 + kxrc) * HROW + hb;
                uint4 sa = *(const uint4*)sp;
                uint4 sb2 = *(const uint4*)(sp + 16);
                __half2 s2 = __hmul2(q2[0], H2(sa.x));
                s2 = __hfma2(q2[1], H2(sa.y), s2);
                s2 = __hfma2(q2[2], H2(sa.z), s2);
                s2 = __hfma2(q2[3], H2(sa.w), s2);
                s2 = __hfma2(q2[4], H2(sb2.x), s2);
                s2 = __hfma2(q2[5], H2(sb2.y), s2);
                s2 = __hfma2(q2[6], H2(sb2.z), s2);
                s2 = __hfma2(q2[7], H2(sb2.w), s2);
                float2 f = __half22float2(s2);
                qsp[i5] = f.x + f.y;
            }

            __half2 a2[15];
            float ssum = 0.f;
#pragma unroll
            for (int tk = 0; tk < 3; tk++)
#pragma unroll
                for (int i5 = 0; i5 < 5; i5++) {
                    int idx = tk * 5 + i5;
                    float e = ex2(a[idx] + qsp[i5]);   // Q pre-scaled
                    e = valid ? e : 0.f;
                    ssum += e;
                    a2[idx] = __floats2half2_rn(e, e);
                }
            ssum += __shfl_xor_sync(0xffffffffu, ssum, 1);
            ssum += __shfl_xor_sync(0xffffffffu, ssum, 2);
            ssum += __shfl_xor_sync(0xffffffffu, ssum, 4);
            float rs = __fdividef(1.f, ssum);

            u64 facc[8];
#pragma unroll
            for (int i = 0; i < 8; i++) facc[i] = 0ull;

#pragma unroll
            for (int tk = 0; tk < 3; tk++) {
                __half2 hc[8];
#pragma unroll
                for (int i = 0; i < 8; i++) hc[i] = __floats2half2_rn(0.f, 0.f);
#pragma unroll
                for (int i5 = 0; i5 < 5; i5++) {
                    const char* vr = Vrh + slot[i5] * SLICEB + (tk * 8 + rl) * HROW + hb;
                    uint4 va = *(const uint4*)vr;
                    uint4 vb = *(const uint4*)(vr + 16);
                    __half2 aa = a2[tk * 5 + i5];
                    hc[0] = __hfma2(aa, H2(va.x), hc[0]);
                    hc[1] = __hfma2(aa, H2(va.y), hc[1]);
                    hc[2] = __hfma2(aa, H2(va.z), hc[2]);
                    hc[3] = __hfma2(aa, H2(va.w), hc[3]);
                    hc[4] = __hfma2(aa, H2(vb.x), hc[4]);
                    hc[5] = __hfma2(aa, H2(vb.y), hc[5]);
                    hc[6] = __hfma2(aa, H2(vb.z), hc[6]);
                    hc[7] = __hfma2(aa, H2(vb.w), hc[7]);
                }
#pragma unroll
                for (int i = 0; i < 8; i++) {
                    float2 f = __half22float2(hc[i]);
                    facc[i] = fadd2(facc[i], pack2(f.x, f.y));
                }
            }
#pragma unroll
            for (int off = 1; off <= 4; off <<= 1)
#pragma unroll
                for (int i = 0; i < 8; i++)
                    facc[i] = fadd2(facc[i], __shfl_xor_sync(0xffffffffu, facc[i], off));

            u64 m0v = (rl & 1) ? facc[1] : facc[0];
            u64 m1v = (rl & 1) ? facc[3] : facc[2];
            u64 m2v = (rl & 1) ? facc[5] : facc[4];
            u64 m3v = (rl & 1) ? facc[7] : facc[6];
            u64 n0v = (rl & 2) ? m1v : m0v;
            u64 n1v = (rl & 2) ? m3v : m2v;
            u64 sv  = (rl & 4) ? n1v : n0v;
            sv = fmul2(sv, pack2(rs, rs));
            float2 pv = unpack2(sv);
            const int n = tq * HW_ + yq * W_ + x0 + qx;
            g_Oh[(size_t)n * 64 + (h << 3) + rl] = h2pack(pv.x, pv.y);
        }

        if (pf) asm volatile("cp.async.wait_group 0;");
        __syncthreads();
    }
}

// ---------------------------------------------------------------------------
extern "C" void kernel_launch(void* const* d_in, const int* in_sizes, int n_in,
                              void* d_out, int out_size)
{
    const float* x    = (const float*)d_in[0];
    const float* Wq   = (const float*)d_in[1];
    const float* Wk   = (const float*)d_in[2];
    const float* Wv   = (const float*)d_in[3];
    const float* Wo   = (const float*)d_in[4];
    const float* temp = (const float*)d_in[5];
    const float* sp   = (const float*)d_in[6];
    float* out = (float*)d_out;

    cudaFuncSetAttribute(qkv_mma_kernel, cudaFuncAttributeMaxDynamicSharedMemorySize, GEMM_SMEM);
    cudaFuncSetAttribute(outproj_mma_kernel, cudaFuncAttributeMaxDynamicSharedMemorySize, GEMM_SMEM);
    cudaFuncSetAttribute(attn_kernel, cudaFuncAttributeMaxDynamicSharedMemorySize, ATTN_SMEM);

    prep_kernel<<<NXB + 5, 256>>>(x, Wq, Wk, Wv, Wo, sp);
    qkv_mma_kernel<<<dim3(NT / 128, 3), 256, GEMM_SMEM>>>(temp, sp);

    attn_kernel<<<dim3(XS, YB), 384, ATTN_SMEM>>>();

    outproj_mma_kernel<<<NT / 128, 256, GEMM_SMEM>>>(out);
}